// round 3
// baseline (speedup 1.0000x reference)
#include <cuda_runtime.h>
#include <math.h>

// Problem dims
#define TSTEPS 512
#define BATCH  64
#define FDIM   256
#define HDIM   1024
#define CDIM   257

// Recurrent persistent-kernel config
#define NCTA   128          // 1024 j-cols / 8 per CTA
#define NJ     8
#define KC     128          // h chunk (k) size staged in smem
#define HPAD   (KC + 4)     // padded row to kill 8-way bank conflicts
#define HBUF   (BATCH * HPAD)        // 8448 floats per buffer
#define SM_W   (4 * NJ * HDIM)       // 32768 floats (128 KB) weights
#define SM_H   (2 * HBUF)            // 16896 floats double-buffered h
#define SM_C   (BATCH * NJ)          // 512 floats cell state
#define SMEM_BYTES ((SM_W + SM_H + SM_C) * 4)   // 200704 B

// ---------------- scratch (static device globals: no allocation allowed) ----
__device__ float g_gx[(size_t)TSTEPS * 4 * BATCH * HDIM];   // 512 MB gates_x
__device__ float g_hs[(size_t)TSTEPS * BATCH * HDIM];       // 128 MB h outputs
__device__ unsigned int g_arrive;
__device__ volatile unsigned int g_release;

// ---------------- packed f32x2 helpers (FFMA2: 2x fp32 FMA throughput) ------
static __device__ __forceinline__ unsigned long long pack2(float a, float b) {
    unsigned long long r;
    asm("mov.b64 %0, {%1, %2};" : "=l"(r) : "f"(a), "f"(b));
    return r;
}
static __device__ __forceinline__ unsigned long long fma2(
    unsigned long long a, unsigned long long b, unsigned long long c) {
    unsigned long long d;
    asm("fma.rn.f32x2 %0, %1, %2, %3;" : "=l"(d) : "l"(a), "l"(b), "l"(c));
    return d;
}
static __device__ __forceinline__ float2 unpack2(unsigned long long a) {
    float2 f;
    asm("mov.b64 {%0, %1}, %2;" : "=f"(f.x), "=f"(f.y) : "l"(a));
    return f;
}
static __device__ __forceinline__ void cp16(void* s, const void* g) {
    unsigned ss = (unsigned)__cvta_generic_to_shared(s);
    asm volatile("cp.async.cg.shared.global [%0], [%1], 16;" :: "r"(ss), "l"(g));
}
static __device__ __forceinline__ float sigmoid_f(float x) {
    return 1.f / (1.f + __expf(-x));
}
static __device__ __forceinline__ float tanh_f(float x) {
    float e = __expf(2.f * x);          // accurate MUFU.EX2-based; saturates safely
    return 1.f - 2.f / (e + 1.f);
}

// ===========================================================================
// Kernel 1: gates_x = x @ Wx^T + b   for 4 gates.
// C[M=32768][N=4096] = X[M,256] * W[N,256]^T, stored permuted into g_gx[t][g][b][j].
// 64x64 tile, 256 threads, 4x4 per thread, f32x2 packed inner product.
// ===========================================================================
__global__ __launch_bounds__(256) void gates_gemm(
    const float* __restrict__ x,
    const float* __restrict__ w0, const float* __restrict__ w1,
    const float* __restrict__ w2, const float* __restrict__ w3,
    const float* __restrict__ b0, const float* __restrict__ b1,
    const float* __restrict__ b2, const float* __restrict__ b3)
{
    __shared__ float As[64][36];   // +4 pad: float4-aligned, 2-way conflicts only
    __shared__ float Bs[64][36];

    const int tid = threadIdx.x;
    const int n0 = blockIdx.x * 64;
    const int m0 = blockIdx.y * 64;
    const int g  = n0 >> 10;          // 1024 % 64 == 0: one gate per block
    const int j0 = n0 & 1023;
    const float* W  = (g == 0) ? w0 : (g == 1) ? w1 : (g == 2) ? w2 : w3;
    const float* Bv = (g == 0) ? b0 : (g == 1) ? b1 : (g == 2) ? b2 : b3;

    const int ty = tid >> 4, tx = tid & 15;

    unsigned long long acc[4][4];
#pragma unroll
    for (int i = 0; i < 4; i++)
#pragma unroll
        for (int j = 0; j < 4; j++) acc[i][j] = 0ull;

    for (int k0 = 0; k0 < FDIM; k0 += 32) {
#pragma unroll
        for (int i = 0; i < 2; i++) {
            int idx = tid + i * 256;
            int r = idx >> 3, c = (idx & 7) * 4;
            *(float4*)(&As[r][c]) = *(const float4*)(x + (size_t)(m0 + r) * FDIM + k0 + c);
            *(float4*)(&Bs[r][c]) = *(const float4*)(W + (size_t)(j0 + r) * FDIM + k0 + c);
        }
        __syncthreads();
#pragma unroll
        for (int kk = 0; kk < 32; kk += 2) {
            unsigned long long rm[4], rn[4];
#pragma unroll
            for (int i = 0; i < 4; i++)
                rm[i] = *(const unsigned long long*)(&As[ty * 4 + i][kk]);
#pragma unroll
            for (int j = 0; j < 4; j++)
                rn[j] = *(const unsigned long long*)(&Bs[tx * 4 + j][kk]);
#pragma unroll
            for (int i = 0; i < 4; i++)
#pragma unroll
                for (int j = 0; j < 4; j++)
                    acc[i][j] = fma2(rm[i], rn[j], acc[i][j]);
        }
        __syncthreads();
    }

    float bj[4];
#pragma unroll
    for (int j = 0; j < 4; j++) bj[j] = Bv[j0 + tx * 4 + j];

#pragma unroll
    for (int i = 0; i < 4; i++) {
        int m = m0 + ty * 4 + i;
        int t = m >> 6, b = m & 63;
#pragma unroll
        for (int j = 0; j < 4; j++) {
            float2 v = unpack2(acc[i][j]);
            int jj = j0 + tx * 4 + j;
            g_gx[(((size_t)t * 4 + g) * BATCH + b) * HDIM + jj] = v.x + v.y + bj[j];
        }
    }
}

// ===========================================================================
// Kernel 2: persistent recurrent LSTM.
// 128 CTAs x 256 threads. CTA ct owns j in [8*ct, 8*ct+8), all 4 gates.
// Weights (4x8x1024 fp32 = 128 KB) resident in SMEM for all 512 steps.
// Cell state c (64x8) resident in SMEM. h broadcast per step via cp.async
// double-buffered chunks. Software grid barrier between steps.
// Thread -> (b = tid>>2, j-pair = (tid&3)*2): 8 f32x2 accumulators.
// ===========================================================================
__global__ __launch_bounds__(256, 1) void lstm_rec(
    const float* __restrict__ wfh, const float* __restrict__ wih,
    const float* __restrict__ woh, const float* __restrict__ wch)
{
    extern __shared__ float sm[];
    float* w_s = sm;                    // 32768
    float* h_s = sm + SM_W;             // 16896
    float* c_s = sm + SM_W + SM_H;      // 512

    const int tid = threadIdx.x;
    const int j0 = blockIdx.x * NJ;

    // --- load weight slice into SMEM (one-time) ---
    for (int i4 = tid; i4 < SM_W / 4; i4 += 256) {
        int f   = i4 * 4;
        int g   = f >> 13;              // 8192 floats per gate
        int rem = f & 8191;
        int jj  = rem >> 10;
        int k   = rem & 1023;
        const float* wsrc = (g == 0) ? wfh : (g == 1) ? wih : (g == 2) ? woh : wch;
        *(float4*)(w_s + f) = *(const float4*)(wsrc + (size_t)(j0 + jj) * HDIM + k);
    }
    __syncthreads();

    const int b   = tid >> 2;
    const int jj0 = (tid & 3) * 2;

    int wof[8];
#pragma unroll
    for (int g = 0; g < 4; g++)
#pragma unroll
        for (int jx = 0; jx < 2; jx++)
            wof[g * 2 + jx] = (g * NJ + jj0 + jx) * HDIM;

    for (int t = 0; t < TSTEPS; t++) {
        // init accumulators with gates_x (lane-lo)
        unsigned long long acc[8];
#pragma unroll
        for (int g = 0; g < 4; g++) {
            float2 gg = *(const float2*)(g_gx +
                (((size_t)t * 4 + g) * BATCH + b) * HDIM + j0 + jj0);
            acc[g * 2 + 0] = pack2(gg.x, 0.f);
            acc[g * 2 + 1] = pack2(gg.y, 0.f);
        }

        if (t > 0) {
            const float* hsrc = g_hs + (size_t)(t - 1) * BATCH * HDIM;

            // prologue: stage chunk 0
#pragma unroll
            for (int i = 0; i < 8; i++) {
                int idx = tid + i * 256;
                int bb = idx >> 5, c4 = (idx & 31) * 4;
                cp16(h_s + bb * HPAD + c4, hsrc + (size_t)bb * HDIM + c4);
            }
            asm volatile("cp.async.commit_group;");

            for (int ch = 0; ch < HDIM / KC; ch++) {
                const int cur = ch & 1;
                if (ch + 1 < HDIM / KC) {
                    float* dst = h_s + ((ch + 1) & 1) * HBUF;
                    int kbase = (ch + 1) * KC;
#pragma unroll
                    for (int i = 0; i < 8; i++) {
                        int idx = tid + i * 256;
                        int bb = idx >> 5, c4 = (idx & 31) * 4;
                        cp16(dst + bb * HPAD + c4, hsrc + (size_t)bb * HDIM + kbase + c4);
                    }
                    asm volatile("cp.async.commit_group;");
                    asm volatile("cp.async.wait_group 1;");
                } else {
                    asm volatile("cp.async.wait_group 0;");
                }
                __syncthreads();

                const float* hr = h_s + cur * HBUF + b * HPAD;
                const float* wk = w_s + ch * KC;
#pragma unroll 8
                for (int kk = 0; kk < KC; kk += 4) {
                    ulonglong2 h2 = *(const ulonglong2*)(hr + kk);
#pragma unroll
                    for (int s = 0; s < 8; s++) {
                        ulonglong2 w2 = *(const ulonglong2*)(wk + wof[s] + kk);
                        acc[s] = fma2(h2.x, w2.x, acc[s]);
                        acc[s] = fma2(h2.y, w2.y, acc[s]);
                    }
                }
                __syncthreads();
            }
        }

        // pointwise gate math
        float z[8];
#pragma unroll
        for (int s = 0; s < 8; s++) {
            float2 u = unpack2(acc[s]);
            z[s] = u.x + u.y;
        }
        float hv[2];
#pragma unroll
        for (int jx = 0; jx < 2; jx++) {
            float f_  = sigmoid_f(z[0 * 2 + jx]);
            float i_  = sigmoid_f(z[1 * 2 + jx]);
            float o_  = sigmoid_f(z[2 * 2 + jx]);
            float a_  = z[3 * 2 + jx];
            float cp  = (t == 0) ? 0.f : c_s[b * NJ + jj0 + jx];
            float c_  = i_ * tanh_f(a_) + f_ * cp;
            c_s[b * NJ + jj0 + jx] = c_;
            hv[jx] = o_ * tanh_f(c_);
        }
        *(float2*)(g_hs + ((size_t)t * BATCH + b) * HDIM + j0 + jj0) =
            make_float2(hv[0], hv[1]);

        // grid barrier (skip after last step)
        if (t < TSTEPS - 1) {
            __threadfence();
            __syncthreads();
            if (tid == 0) {
                unsigned prev = atomicAdd(&g_arrive, 1u);
                unsigned target = (unsigned)(t + 1) * NCTA;
                if (prev == target - 1) {
                    g_release = (unsigned)(t + 1);
                } else {
                    while (g_release < (unsigned)(t + 1)) { }
                }
                __threadfence();
            }
            __syncthreads();
        }
    }
}

// ===========================================================================
// Kernel 3: out = hs @ fco_w^T + fco_b.  M=32768, N=257, K=1024. Guarded tiles.
// ===========================================================================
__global__ __launch_bounds__(256) void out_gemm(
    const float* __restrict__ fw, const float* __restrict__ fb,
    float* __restrict__ out)
{
    __shared__ float As[64][36];
    __shared__ float Bs[64][36];

    const int tid = threadIdx.x;
    const int n0 = blockIdx.x * 64;
    const int m0 = blockIdx.y * 64;
    const int ty = tid >> 4, tx = tid & 15;

    unsigned long long acc[4][4];
#pragma unroll
    for (int i = 0; i < 4; i++)
#pragma unroll
        for (int j = 0; j < 4; j++) acc[i][j] = 0ull;

    for (int k0 = 0; k0 < HDIM; k0 += 32) {
#pragma unroll
        for (int i = 0; i < 2; i++) {
            int idx = tid + i * 256;
            int r = idx >> 3, c = (idx & 7) * 4;
            *(float4*)(&As[r][c]) = *(const float4*)(g_hs + (size_t)(m0 + r) * HDIM + k0 + c);
            int jr = n0 + r;
            float4 b4 = make_float4(0.f, 0.f, 0.f, 0.f);
            if (jr < CDIM)
                b4 = *(const float4*)(fw + (size_t)jr * HDIM + k0 + c);
            *(float4*)(&Bs[r][c]) = b4;
        }
        __syncthreads();
#pragma unroll
        for (int kk = 0; kk < 32; kk += 2) {
            unsigned long long rm[4], rn[4];
#pragma unroll
            for (int i = 0; i < 4; i++)
                rm[i] = *(const unsigned long long*)(&As[ty * 4 + i][kk]);
#pragma unroll
            for (int j = 0; j < 4; j++)
                rn[j] = *(const unsigned long long*)(&Bs[tx * 4 + j][kk]);
#pragma unroll
            for (int i = 0; i < 4; i++)
#pragma unroll
                for (int j = 0; j < 4; j++)
                    acc[i][j] = fma2(rm[i], rn[j], acc[i][j]);
        }
        __syncthreads();
    }

#pragma unroll
    for (int i = 0; i < 4; i++) {
        int m = m0 + ty * 4 + i;
#pragma unroll
        for (int j = 0; j < 4; j++) {
            int n = n0 + tx * 4 + j;
            if (n < CDIM) {
                float2 v = unpack2(acc[i][j]);
                out[(size_t)m * CDIM + n] = v.x + v.y + fb[n];
            }
        }
    }
}

__global__ void init_k() { g_arrive = 0; g_release = 0; }

// ===========================================================================
extern "C" void kernel_launch(void* const* d_in, const int* in_sizes, int n_in,
                              void* d_out, int out_size)
{
    const float* x     = (const float*)d_in[0];
    const float* wfx_w = (const float*)d_in[1];
    const float* wfx_b = (const float*)d_in[2];
    const float* wix_w = (const float*)d_in[3];
    const float* wix_b = (const float*)d_in[4];
    const float* wox_w = (const float*)d_in[5];
    const float* wox_b = (const float*)d_in[6];
    const float* wcx_w = (const float*)d_in[7];
    const float* wcx_b = (const float*)d_in[8];
    const float* wfh_w = (const float*)d_in[9];
    const float* wih_w = (const float*)d_in[10];
    const float* woh_w = (const float*)d_in[11];
    const float* wch_w = (const float*)d_in[12];
    const float* fco_w = (const float*)d_in[13];
    const float* fco_b = (const float*)d_in[14];
    float* out = (float*)d_out;

    cudaFuncSetAttribute(lstm_rec, cudaFuncAttributeMaxDynamicSharedMemorySize,
                         SMEM_BYTES);

    init_k<<<1, 1>>>();
    gates_gemm<<<dim3(4 * HDIM / 64, TSTEPS * BATCH / 64), 256>>>(
        x, wfx_w, wix_w, wox_w, wcx_w, wfx_b, wix_b, wox_b, wcx_b);
    lstm_rec<<<NCTA, 256, SMEM_BYTES>>>(wfh_w, wih_w, woh_w, wch_w);
    out_gemm<<<dim3((CDIM + 63) / 64, TSTEPS * BATCH / 64), 256>>>(
        fco_w, fco_b, out);
}

// round 4
// speedup vs baseline: 1.0018x; 1.0018x over previous
#include <cuda_runtime.h>
#include <math.h>

// Problem dims
#define TSTEPS 512
#define BATCH  64
#define FDIM   256
#define HDIM   1024
#define CDIM   257

// Recurrent persistent-kernel config
#define NCTA   128          // 1024 j-cols / 8 per CTA
#define NJ     8
#define KC     128          // h chunk (k) size staged in smem
#define HPAD   (KC + 4)     // padded row to kill 8-way bank conflicts
#define HBUF   (BATCH * HPAD)        // 8448 floats per buffer
#define SM_W   (4 * NJ * HDIM)       // 32768 floats (128 KB) weights
#define SM_H   (2 * HBUF)            // 16896 floats double-buffered h
#define SM_C   (BATCH * NJ)          // 512 floats cell state
#define SMEM_BYTES ((SM_W + SM_H + SM_C) * 4)   // 200704 B

// ---------------- scratch (static device globals: no allocation allowed) ----
__device__ float g_gx[(size_t)TSTEPS * 4 * BATCH * HDIM];   // 512 MB gates_x
__device__ float g_hs[(size_t)TSTEPS * BATCH * HDIM];       // 128 MB h outputs
__device__ unsigned int g_arrive;
__device__ volatile unsigned int g_release;

// ---------------- packed f32x2 helpers (FFMA2: 2x fp32 FMA throughput) ------
static __device__ __forceinline__ unsigned long long pack2(float a, float b) {
    unsigned long long r;
    asm("mov.b64 %0, {%1, %2};" : "=l"(r) : "f"(a), "f"(b));
    return r;
}
static __device__ __forceinline__ unsigned long long fma2(
    unsigned long long a, unsigned long long b, unsigned long long c) {
    unsigned long long d;
    asm("fma.rn.f32x2 %0, %1, %2, %3;" : "=l"(d) : "l"(a), "l"(b), "l"(c));
    return d;
}
static __device__ __forceinline__ float2 unpack2(unsigned long long a) {
    float2 f;
    asm("mov.b64 {%0, %1}, %2;" : "=f"(f.x), "=f"(f.y) : "l"(a));
    return f;
}
static __device__ __forceinline__ void cp16(void* s, const void* g) {
    unsigned ss = (unsigned)__cvta_generic_to_shared(s);
    asm volatile("cp.async.cg.shared.global [%0], [%1], 16;" :: "r"(ss), "l"(g));
}
static __device__ __forceinline__ float sigmoid_f(float x) {
    return 1.f / (1.f + __expf(-x));
}
static __device__ __forceinline__ float tanh_f(float x) {
    float e = __expf(2.f * x);          // accurate MUFU.EX2-based; saturates safely
    return 1.f - 2.f / (e + 1.f);
}

// ===========================================================================
// Kernel 1: gates_x = x @ Wx^T + b   for 4 gates.
// C[M=32768][N=4096] = X[M,256] * W[N,256]^T, stored permuted into g_gx[t][g][b][j].
// 64x64 tile, 256 threads, 4x4 per thread, f32x2 packed inner product.
// ===========================================================================
__global__ __launch_bounds__(256) void gates_gemm(
    const float* __restrict__ x,
    const float* __restrict__ w0, const float* __restrict__ w1,
    const float* __restrict__ w2, const float* __restrict__ w3,
    const float* __restrict__ b0, const float* __restrict__ b1,
    const float* __restrict__ b2, const float* __restrict__ b3)
{
    __shared__ float As[64][36];   // +4 pad: float4-aligned, 2-way conflicts only
    __shared__ float Bs[64][36];

    const int tid = threadIdx.x;
    const int n0 = blockIdx.x * 64;
    const int m0 = blockIdx.y * 64;
    const int g  = n0 >> 10;          // 1024 % 64 == 0: one gate per block
    const int j0 = n0 & 1023;
    const float* W  = (g == 0) ? w0 : (g == 1) ? w1 : (g == 2) ? w2 : w3;
    const float* Bv = (g == 0) ? b0 : (g == 1) ? b1 : (g == 2) ? b2 : b3;

    const int ty = tid >> 4, tx = tid & 15;

    unsigned long long acc[4][4];
#pragma unroll
    for (int i = 0; i < 4; i++)
#pragma unroll
        for (int j = 0; j < 4; j++) acc[i][j] = 0ull;

    for (int k0 = 0; k0 < FDIM; k0 += 32) {
#pragma unroll
        for (int i = 0; i < 2; i++) {
            int idx = tid + i * 256;
            int r = idx >> 3, c = (idx & 7) * 4;
            *(float4*)(&As[r][c]) = *(const float4*)(x + (size_t)(m0 + r) * FDIM + k0 + c);
            *(float4*)(&Bs[r][c]) = *(const float4*)(W + (size_t)(j0 + r) * FDIM + k0 + c);
        }
        __syncthreads();
#pragma unroll
        for (int kk = 0; kk < 32; kk += 2) {
            unsigned long long rm[4], rn[4];
#pragma unroll
            for (int i = 0; i < 4; i++)
                rm[i] = *(const unsigned long long*)(&As[ty * 4 + i][kk]);
#pragma unroll
            for (int j = 0; j < 4; j++)
                rn[j] = *(const unsigned long long*)(&Bs[tx * 4 + j][kk]);
#pragma unroll
            for (int i = 0; i < 4; i++)
#pragma unroll
                for (int j = 0; j < 4; j++)
                    acc[i][j] = fma2(rm[i], rn[j], acc[i][j]);
        }
        __syncthreads();
    }

    float bj[4];
#pragma unroll
    for (int j = 0; j < 4; j++) bj[j] = Bv[j0 + tx * 4 + j];

#pragma unroll
    for (int i = 0; i < 4; i++) {
        int m = m0 + ty * 4 + i;
        int t = m >> 6, b = m & 63;
#pragma unroll
        for (int j = 0; j < 4; j++) {
            float2 v = unpack2(acc[i][j]);
            int jj = j0 + tx * 4 + j;
            g_gx[(((size_t)t * 4 + g) * BATCH + b) * HDIM + jj] = v.x + v.y + bj[j];
        }
    }
}

// ===========================================================================
// Kernel 2: persistent recurrent LSTM.
// 128 CTAs x 256 threads. CTA ct owns j in [8*ct, 8*ct+8), all 4 gates.
// Weights (4x8x1024 fp32 = 128 KB) resident in SMEM for all 512 steps.
// Cell state c (64x8) resident in SMEM. h broadcast per step via cp.async
// double-buffered chunks. Software grid barrier between steps.
// Thread -> (b = tid>>2, j-pair = (tid&3)*2): 8 f32x2 accumulators.
// ===========================================================================
__global__ __launch_bounds__(256, 1) void lstm_rec(
    const float* __restrict__ wfh, const float* __restrict__ wih,
    const float* __restrict__ woh, const float* __restrict__ wch)
{
    extern __shared__ float sm[];
    float* w_s = sm;                    // 32768
    float* h_s = sm + SM_W;             // 16896
    float* c_s = sm + SM_W + SM_H;      // 512

    const int tid = threadIdx.x;
    const int j0 = blockIdx.x * NJ;

    // --- load weight slice into SMEM (one-time) ---
    for (int i4 = tid; i4 < SM_W / 4; i4 += 256) {
        int f   = i4 * 4;
        int g   = f >> 13;              // 8192 floats per gate
        int rem = f & 8191;
        int jj  = rem >> 10;
        int k   = rem & 1023;
        const float* wsrc = (g == 0) ? wfh : (g == 1) ? wih : (g == 2) ? woh : wch;
        *(float4*)(w_s + f) = *(const float4*)(wsrc + (size_t)(j0 + jj) * HDIM + k);
    }
    __syncthreads();

    const int b   = tid >> 2;
    const int jj0 = (tid & 3) * 2;

    int wof[8];
#pragma unroll
    for (int g = 0; g < 4; g++)
#pragma unroll
        for (int jx = 0; jx < 2; jx++)
            wof[g * 2 + jx] = (g * NJ + jj0 + jx) * HDIM;

    for (int t = 0; t < TSTEPS; t++) {
        // init accumulators with gates_x (lane-lo)
        unsigned long long acc[8];
#pragma unroll
        for (int g = 0; g < 4; g++) {
            float2 gg = *(const float2*)(g_gx +
                (((size_t)t * 4 + g) * BATCH + b) * HDIM + j0 + jj0);
            acc[g * 2 + 0] = pack2(gg.x, 0.f);
            acc[g * 2 + 1] = pack2(gg.y, 0.f);
        }

        if (t > 0) {
            const float* hsrc = g_hs + (size_t)(t - 1) * BATCH * HDIM;

            // prologue: stage chunk 0
#pragma unroll
            for (int i = 0; i < 8; i++) {
                int idx = tid + i * 256;
                int bb = idx >> 5, c4 = (idx & 31) * 4;
                cp16(h_s + bb * HPAD + c4, hsrc + (size_t)bb * HDIM + c4);
            }
            asm volatile("cp.async.commit_group;");

            for (int ch = 0; ch < HDIM / KC; ch++) {
                const int cur = ch & 1;
                if (ch + 1 < HDIM / KC) {
                    float* dst = h_s + ((ch + 1) & 1) * HBUF;
                    int kbase = (ch + 1) * KC;
#pragma unroll
                    for (int i = 0; i < 8; i++) {
                        int idx = tid + i * 256;
                        int bb = idx >> 5, c4 = (idx & 31) * 4;
                        cp16(dst + bb * HPAD + c4, hsrc + (size_t)bb * HDIM + kbase + c4);
                    }
                    asm volatile("cp.async.commit_group;");
                    asm volatile("cp.async.wait_group 1;");
                } else {
                    asm volatile("cp.async.wait_group 0;");
                }
                __syncthreads();

                const float* hr = h_s + cur * HBUF + b * HPAD;
                const float* wk = w_s + ch * KC;
#pragma unroll 8
                for (int kk = 0; kk < KC; kk += 4) {
                    ulonglong2 h2 = *(const ulonglong2*)(hr + kk);
#pragma unroll
                    for (int s = 0; s < 8; s++) {
                        ulonglong2 w2 = *(const ulonglong2*)(wk + wof[s] + kk);
                        acc[s] = fma2(h2.x, w2.x, acc[s]);
                        acc[s] = fma2(h2.y, w2.y, acc[s]);
                    }
                }
                __syncthreads();
            }
        }

        // pointwise gate math
        float z[8];
#pragma unroll
        for (int s = 0; s < 8; s++) {
            float2 u = unpack2(acc[s]);
            z[s] = u.x + u.y;
        }
        float hv[2];
#pragma unroll
        for (int jx = 0; jx < 2; jx++) {
            float f_  = sigmoid_f(z[0 * 2 + jx]);
            float i_  = sigmoid_f(z[1 * 2 + jx]);
            float o_  = sigmoid_f(z[2 * 2 + jx]);
            float a_  = z[3 * 2 + jx];
            float cp  = (t == 0) ? 0.f : c_s[b * NJ + jj0 + jx];
            float c_  = i_ * tanh_f(a_) + f_ * cp;
            c_s[b * NJ + jj0 + jx] = c_;
            hv[jx] = o_ * tanh_f(c_);
        }
        *(float2*)(g_hs + ((size_t)t * BATCH + b) * HDIM + j0 + jj0) =
            make_float2(hv[0], hv[1]);

        // grid barrier (skip after last step)
        if (t < TSTEPS - 1) {
            __threadfence();
            __syncthreads();
            if (tid == 0) {
                unsigned prev = atomicAdd(&g_arrive, 1u);
                unsigned target = (unsigned)(t + 1) * NCTA;
                if (prev == target - 1) {
                    g_release = (unsigned)(t + 1);
                } else {
                    while (g_release < (unsigned)(t + 1)) { }
                }
                __threadfence();
            }
            __syncthreads();
        }
    }
}

// ===========================================================================
// Kernel 3: out = hs @ fco_w^T + fco_b.  M=32768, N=257, K=1024. Guarded tiles.
// ===========================================================================
__global__ __launch_bounds__(256) void out_gemm(
    const float* __restrict__ fw, const float* __restrict__ fb,
    float* __restrict__ out)
{
    __shared__ float As[64][36];
    __shared__ float Bs[64][36];

    const int tid = threadIdx.x;
    const int n0 = blockIdx.x * 64;
    const int m0 = blockIdx.y * 64;
    const int ty = tid >> 4, tx = tid & 15;

    unsigned long long acc[4][4];
#pragma unroll
    for (int i = 0; i < 4; i++)
#pragma unroll
        for (int j = 0; j < 4; j++) acc[i][j] = 0ull;

    for (int k0 = 0; k0 < HDIM; k0 += 32) {
#pragma unroll
        for (int i = 0; i < 2; i++) {
            int idx = tid + i * 256;
            int r = idx >> 3, c = (idx & 7) * 4;
            *(float4*)(&As[r][c]) = *(const float4*)(g_hs + (size_t)(m0 + r) * HDIM + k0 + c);
            int jr = n0 + r;
            float4 b4 = make_float4(0.f, 0.f, 0.f, 0.f);
            if (jr < CDIM)
                b4 = *(const float4*)(fw + (size_t)jr * HDIM + k0 + c);
            *(float4*)(&Bs[r][c]) = b4;
        }
        __syncthreads();
#pragma unroll
        for (int kk = 0; kk < 32; kk += 2) {
            unsigned long long rm[4], rn[4];
#pragma unroll
            for (int i = 0; i < 4; i++)
                rm[i] = *(const unsigned long long*)(&As[ty * 4 + i][kk]);
#pragma unroll
            for (int j = 0; j < 4; j++)
                rn[j] = *(const unsigned long long*)(&Bs[tx * 4 + j][kk]);
#pragma unroll
            for (int i = 0; i < 4; i++)
#pragma unroll
                for (int j = 0; j < 4; j++)
                    acc[i][j] = fma2(rm[i], rn[j], acc[i][j]);
        }
        __syncthreads();
    }

#pragma unroll
    for (int i = 0; i < 4; i++) {
        int m = m0 + ty * 4 + i;
#pragma unroll
        for (int j = 0; j < 4; j++) {
            int n = n0 + tx * 4 + j;
            if (n < CDIM) {
                float2 v = unpack2(acc[i][j]);
                out[(size_t)m * CDIM + n] = v.x + v.y + fb[n];
            }
        }
    }
}

__global__ void init_k() { g_arrive = 0; g_release = 0; }

// ===========================================================================
extern "C" void kernel_launch(void* const* d_in, const int* in_sizes, int n_in,
                              void* d_out, int out_size)
{
    const float* x     = (const float*)d_in[0];
    const float* wfx_w = (const float*)d_in[1];
    const float* wfx_b = (const float*)d_in[2];
    const float* wix_w = (const float*)d_in[3];
    const float* wix_b = (const float*)d_in[4];
    const float* wox_w = (const float*)d_in[5];
    const float* wox_b = (const float*)d_in[6];
    const float* wcx_w = (const float*)d_in[7];
    const float* wcx_b = (const float*)d_in[8];
    const float* wfh_w = (const float*)d_in[9];
    const float* wih_w = (const float*)d_in[10];
    const float* woh_w = (const float*)d_in[11];
    const float* wch_w = (const float*)d_in[12];
    const float* fco_w = (const float*)d_in[13];
    const float* fco_b = (const float*)d_in[14];
    float* out = (float*)d_out;

    cudaFuncSetAttribute(lstm_rec, cudaFuncAttributeMaxDynamicSharedMemorySize,
                         SMEM_BYTES);

    init_k<<<1, 1>>>();
    gates_gemm<<<dim3(4 * HDIM / 64, TSTEPS * BATCH / 64), 256>>>(
        x, wfx_w, wix_w, wox_w, wcx_w, wfx_b, wix_b, wox_b, wcx_b);
    lstm_rec<<<NCTA, 256, SMEM_BYTES>>>(wfh_w, wih_w, woh_w, wch_w);
    out_gemm<<<dim3((CDIM + 63) / 64, TSTEPS * BATCH / 64), 256>>>(
        fco_w, fco_b, out);
}

// round 5
// speedup vs baseline: 5.1174x; 5.1080x over previous
#include <cuda_runtime.h>
#include <math.h>

typedef unsigned long long ull;

#define TSTEPS 512
#define BATCH  64
#define FDIM   256
#define HDIM   1024
#define CDIM   257
#define NCTA   128
#define NJ     8

// lstm_rec dynamic smem layout (bytes)
#define OFF_H0   131072            // after 16384 ull dup-packed weights
#define OFF_H1   163840
#define OFF_RED  196608
#define OFF_MB   229376
#define SMEM_REC 229440

__device__ float g_gx[(size_t)TSTEPS * 4 * BATCH * HDIM];   // [t][g][b][j]
__device__ float g_hs[(size_t)TSTEPS * BATCH * HDIM];       // [t][b][j] natural
__device__ float g_hst[(size_t)TSTEPS * HDIM * BATCH];      // [t][j][b] transposed
__device__ unsigned g_arrive;
__device__ volatile unsigned g_release;

static __device__ __forceinline__ ull pack2(float a, float b) {
    ull r; asm("mov.b64 %0, {%1, %2};" : "=l"(r) : "f"(a), "f"(b)); return r;
}
static __device__ __forceinline__ ull fma2(ull a, ull b, ull c) {
    ull d; asm("fma.rn.f32x2 %0, %1, %2, %3;" : "=l"(d) : "l"(a), "l"(b), "l"(c));
    return d;
}
static __device__ __forceinline__ float2 unpack2(ull a) {
    float2 f; asm("mov.b64 {%0, %1}, %2;" : "=f"(f.x), "=f"(f.y) : "l"(a)); return f;
}
static __device__ __forceinline__ float sigmoid_f(float x) {
    return 1.f / (1.f + __expf(-x));
}
static __device__ __forceinline__ float tanh_f(float x) {
    float e = __expf(2.f * x);
    return 1.f - 2.f / (e + 1.f);
}
static __device__ __forceinline__ unsigned smem_u32(const void* p) {
    return (unsigned)__cvta_generic_to_shared(p);
}
static __device__ __forceinline__ void mbar_init(unsigned a) {
    asm volatile("mbarrier.init.shared.b64 [%0], 1;" :: "r"(a) : "memory");
}
static __device__ __forceinline__ void bulk_ld(unsigned dst, const float* src,
                                               unsigned bytes, unsigned mbar) {
    asm volatile("mbarrier.arrive.expect_tx.shared.b64 _, [%0], %1;"
                 :: "r"(mbar), "r"(bytes) : "memory");
    asm volatile("cp.async.bulk.shared::cluster.global.mbarrier::complete_tx::bytes "
                 "[%0], [%1], %2, [%3];"
                 :: "r"(dst), "l"(src), "r"(bytes), "r"(mbar) : "memory");
}
static __device__ __forceinline__ void mbar_wait(unsigned mbar, unsigned phase) {
    asm volatile(
        "{\n\t.reg .pred P;\n\t"
        "LW_%=:\n\t"
        "mbarrier.try_wait.parity.acquire.cta.shared::cta.b64 P, [%0], %1, 0x989680;\n\t"
        "@P bra LD_%=;\n\t"
        "bra LW_%=;\n\t"
        "LD_%=:\n\t}"
        :: "r"(mbar), "r"(phase) : "memory");
}

// ===========================================================================
// Kernel 1: gates_x (unchanged from R2, known correct)
// ===========================================================================
__global__ __launch_bounds__(256) void gates_gemm(
    const float* __restrict__ x,
    const float* __restrict__ w0, const float* __restrict__ w1,
    const float* __restrict__ w2, const float* __restrict__ w3,
    const float* __restrict__ b0, const float* __restrict__ b1,
    const float* __restrict__ b2, const float* __restrict__ b3)
{
    __shared__ float As[64][36];
    __shared__ float Bs[64][36];

    const int tid = threadIdx.x;
    const int n0 = blockIdx.x * 64;
    const int m0 = blockIdx.y * 64;
    const int g  = n0 >> 10;
    const int j0 = n0 & 1023;
    const float* W  = (g == 0) ? w0 : (g == 1) ? w1 : (g == 2) ? w2 : w3;
    const float* Bv = (g == 0) ? b0 : (g == 1) ? b1 : (g == 2) ? b2 : b3;
    const int ty = tid >> 4, tx = tid & 15;

    ull acc[4][4];
#pragma unroll
    for (int i = 0; i < 4; i++)
#pragma unroll
        for (int j = 0; j < 4; j++) acc[i][j] = 0ull;

    for (int k0 = 0; k0 < FDIM; k0 += 32) {
#pragma unroll
        for (int i = 0; i < 2; i++) {
            int idx = tid + i * 256;
            int r = idx >> 3, c = (idx & 7) * 4;
            *(float4*)(&As[r][c]) = *(const float4*)(x + (size_t)(m0 + r) * FDIM + k0 + c);
            *(float4*)(&Bs[r][c]) = *(const float4*)(W + (size_t)(j0 + r) * FDIM + k0 + c);
        }
        __syncthreads();
#pragma unroll
        for (int kk = 0; kk < 32; kk += 2) {
            ull rm[4], rn[4];
#pragma unroll
            for (int i = 0; i < 4; i++) rm[i] = *(const ull*)(&As[ty * 4 + i][kk]);
#pragma unroll
            for (int j = 0; j < 4; j++) rn[j] = *(const ull*)(&Bs[tx * 4 + j][kk]);
#pragma unroll
            for (int i = 0; i < 4; i++)
#pragma unroll
                for (int j = 0; j < 4; j++)
                    acc[i][j] = fma2(rm[i], rn[j], acc[i][j]);
        }
        __syncthreads();
    }

    float bj[4];
#pragma unroll
    for (int j = 0; j < 4; j++) bj[j] = Bv[j0 + tx * 4 + j];

#pragma unroll
    for (int i = 0; i < 4; i++) {
        int m = m0 + ty * 4 + i;
        int t = m >> 6, b = m & 63;
#pragma unroll
        for (int j = 0; j < 4; j++) {
            float2 v = unpack2(acc[i][j]);
            int jj = j0 + tx * 4 + j;
            g_gx[(((size_t)t * 4 + g) * BATCH + b) * HDIM + jj] = v.x + v.y + bj[j];
        }
    }
}

// ===========================================================================
// Kernel 2: persistent recurrence, conflict-free.
// thread producer role: bp=tid&31 (batch pair 2bp,2bp+1), ks=(tid>>5)&3 (k split),
//                       jg=tid>>7 (gate half). 16 f32x2 accs = 8 (g,jp) x 2 b.
// Weight smem: wp[(g*4+jp)*1024 + k] = (w[j0+2jp][k], w[j0+2jp+1][k]) -> all
// weight LDS.128 warp-uniform (broadcast). h via bulk-copy of transposed
// [k][b] chunks; h LDS.64 contiguous. Cross-ks reduction through smem.
// thread consumer role: jq=tid>>6, bc=tid&63 -> finalizes j pair (j0+2jq,+1), b=bc.
// ===========================================================================
__global__ __launch_bounds__(256, 1) void lstm_rec(
    const float* __restrict__ wfh, const float* __restrict__ wih,
    const float* __restrict__ woh, const float* __restrict__ wch)
{
    extern __shared__ unsigned char sm[];
    ull*   wp   = (ull*)sm;
    float* hbA  = (float*)(sm + OFF_H0);
    float* hbB  = (float*)(sm + OFF_H1);
    ull*   red  = (ull*)(sm + OFF_RED);
    const unsigned mb0 = smem_u32(sm + OFF_MB), mb1 = mb0 + 8;

    const int tid = threadIdx.x;
    const int bp = tid & 31, ks = (tid >> 5) & 3, jg = tid >> 7;
    const int jq = tid >> 6, bc = tid & 63;
    const int j0 = blockIdx.x * NJ;

    if (tid == 0) {
        mbar_init(mb0); mbar_init(mb1);
        asm volatile("fence.proxy.async.shared::cta;" ::: "memory");
    }
    // one-time duplicate-pack of weight slice
    for (int it = tid; it < 4096; it += 256) {
        int g = it >> 10, rem = it & 1023, jp = rem >> 8, k4 = (rem & 255) * 4;
        const float* W = (g == 0) ? wfh : (g == 1) ? wih : (g == 2) ? woh : wch;
        float4 a = *(const float4*)(W + (size_t)(j0 + 2 * jp)     * HDIM + k4);
        float4 c = *(const float4*)(W + (size_t)(j0 + 2 * jp + 1) * HDIM + k4);
        ull* d = wp + (g * 4 + jp) * HDIM + k4;
        d[0] = pack2(a.x, c.x); d[1] = pack2(a.y, c.y);
        d[2] = pack2(a.z, c.z); d[3] = pack2(a.w, c.w);
    }
    __syncthreads();

    float cc0 = 0.f, cc1 = 0.f;
    unsigned ph0 = 0, ph1 = 0;
    const ull* wbase = wp + jg * 8 * HDIM;

    for (int t = 0; t < TSTEPS; t++) {
        float2 gx[4];
#pragma unroll
        for (int g = 0; g < 4; g++)
            gx[g] = *(const float2*)(g_gx +
                (((size_t)t * 4 + g) * BATCH + bc) * HDIM + j0 + 2 * jq);

        ull acc[16];
#pragma unroll
        for (int s = 0; s < 16; s++) acc[s] = 0ull;

        if (t > 0) {
            const float* hsrc = g_hst + (size_t)(t - 1) * HDIM * BATCH;
            if (tid == 0) {
                bulk_ld(smem_u32(hbA), hsrc,        32768, mb0);
                bulk_ld(smem_u32(hbB), hsrc + 8192, 32768, mb1);
            }
#pragma unroll 1
            for (int ch = 0; ch < 8; ch++) {
                if (ch & 1) { mbar_wait(mb1, ph1); ph1 ^= 1; }
                else        { mbar_wait(mb0, ph0); ph0 ^= 1; }

                const float* hq = ((ch & 1) ? hbB : hbA) + ks * 32 * 64 + 2 * bp;
                const ull*   wk = wbase + ch * 128 + ks * 32;
#pragma unroll 4
                for (int kk = 0; kk < 32; kk += 2) {
                    float2 h0 = *(const float2*)(hq + kk * 64);
                    float2 h1 = *(const float2*)(hq + kk * 64 + 64);
                    ull a00 = pack2(h0.x, h0.x), a01 = pack2(h0.y, h0.y);
                    ull a10 = pack2(h1.x, h1.x), a11 = pack2(h1.y, h1.y);
#pragma unroll
                    for (int s = 0; s < 8; s++) {
                        ulonglong2 w = *(const ulonglong2*)(wk + s * HDIM + kk);
                        acc[2*s]   = fma2(a00, w.x, acc[2*s]);
                        acc[2*s]   = fma2(a10, w.y, acc[2*s]);
                        acc[2*s+1] = fma2(a01, w.x, acc[2*s+1]);
                        acc[2*s+1] = fma2(a11, w.y, acc[2*s+1]);
                    }
                }
                __syncthreads();
                if (tid == 0 && ch < 6)
                    bulk_ld(smem_u32((ch & 1) ? hbB : hbA),
                            hsrc + (ch + 2) * 8192, 32768, (ch & 1) ? mb1 : mb0);
            }
        }

        // reduction: producers write partials (b-pair packed, conflict-free)
#pragma unroll
        for (int s = 0; s < 8; s++) {
            int gjp = jg * 8 + s;
            *(ulonglong2*)(red + (gjp * 4 + ks) * 64 + 2 * bp) =
                make_ulonglong2(acc[2*s], acc[2*s+1]);
        }
        __syncthreads();

        // consumer: sum 4 partials + gx, gate math for (j0+2jq, j0+2jq+1, bc)
        float z0[4], z1[4];
#pragma unroll
        for (int g = 0; g < 4; g++) {
            float sx = gx[g].x, sy = gx[g].y;
#pragma unroll
            for (int q = 0; q < 4; q++) {
                float2 p = unpack2(red[((g * 4 + jq) * 4 + q) * 64 + bc]);
                sx += p.x; sy += p.y;
            }
            z0[g] = sx; z1[g] = sy;
        }
        float cp0 = (t == 0) ? 0.f : cc0;
        float cp1 = (t == 0) ? 0.f : cc1;
        cc0 = sigmoid_f(z0[1]) * tanh_f(z0[3]) + sigmoid_f(z0[0]) * cp0;
        cc1 = sigmoid_f(z1[1]) * tanh_f(z1[3]) + sigmoid_f(z1[0]) * cp1;
        float hv0 = sigmoid_f(z0[2]) * tanh_f(cc0);
        float hv1 = sigmoid_f(z1[2]) * tanh_f(cc1);

        *(float2*)(g_hs + ((size_t)t * BATCH + bc) * HDIM + j0 + 2 * jq) =
            make_float2(hv0, hv1);
        size_t tb = ((size_t)t * HDIM + j0 + 2 * jq) * BATCH + bc;
        g_hst[tb]         = hv0;
        g_hst[tb + BATCH] = hv1;

        if (t < TSTEPS - 1) {
            __threadfence();
            __syncthreads();
            if (tid == 0) {
                unsigned prev = atomicAdd(&g_arrive, 1u);
                unsigned target = (unsigned)(t + 1) * NCTA;
                if (prev == target - 1) {
                    g_release = (unsigned)(t + 1);
                } else {
                    while (g_release < (unsigned)(t + 1)) { }
                }
                __threadfence();
            }
            __syncthreads();
        }
    }
}

// ===========================================================================
// Kernel 3: out = hs @ fco^T + b (unchanged from R2, reads natural g_hs)
// ===========================================================================
__global__ __launch_bounds__(256) void out_gemm(
    const float* __restrict__ fw, const float* __restrict__ fb,
    float* __restrict__ out)
{
    __shared__ float As[64][36];
    __shared__ float Bs[64][36];

    const int tid = threadIdx.x;
    const int n0 = blockIdx.x * 64;
    const int m0 = blockIdx.y * 64;
    const int ty = tid >> 4, tx = tid & 15;

    ull acc[4][4];
#pragma unroll
    for (int i = 0; i < 4; i++)
#pragma unroll
        for (int j = 0; j < 4; j++) acc[i][j] = 0ull;

    for (int k0 = 0; k0 < HDIM; k0 += 32) {
#pragma unroll
        for (int i = 0; i < 2; i++) {
            int idx = tid + i * 256;
            int r = idx >> 3, c = (idx & 7) * 4;
            *(float4*)(&As[r][c]) = *(const float4*)(g_hs + (size_t)(m0 + r) * HDIM + k0 + c);
            int jr = n0 + r;
            float4 b4 = make_float4(0.f, 0.f, 0.f, 0.f);
            if (jr < CDIM)
                b4 = *(const float4*)(fw + (size_t)jr * HDIM + k0 + c);
            *(float4*)(&Bs[r][c]) = b4;
        }
        __syncthreads();
#pragma unroll
        for (int kk = 0; kk < 32; kk += 2) {
            ull rm[4], rn[4];
#pragma unroll
            for (int i = 0; i < 4; i++) rm[i] = *(const ull*)(&As[ty * 4 + i][kk]);
#pragma unroll
            for (int j = 0; j < 4; j++) rn[j] = *(const ull*)(&Bs[tx * 4 + j][kk]);
#pragma unroll
            for (int i = 0; i < 4; i++)
#pragma unroll
                for (int j = 0; j < 4; j++)
                    acc[i][j] = fma2(rm[i], rn[j], acc[i][j]);
        }
        __syncthreads();
    }

#pragma unroll
    for (int i = 0; i < 4; i++) {
        int m = m0 + ty * 4 + i;
#pragma unroll
        for (int j = 0; j < 4; j++) {
            int n = n0 + tx * 4 + j;
            if (n < CDIM) {
                float2 v = unpack2(acc[i][j]);
                out[(size_t)m * CDIM + n] = v.x + v.y + fb[n];
            }
        }
    }
}

__global__ void init_k() { g_arrive = 0; g_release = 0; }

extern "C" void kernel_launch(void* const* d_in, const int* in_sizes, int n_in,
                              void* d_out, int out_size)
{
    const float* x     = (const float*)d_in[0];
    const float* wfx_w = (const float*)d_in[1];
    const float* wfx_b = (const float*)d_in[2];
    const float* wix_w = (const float*)d_in[3];
    const float* wix_b = (const float*)d_in[4];
    const float* wox_w = (const float*)d_in[5];
    const float* wox_b = (const float*)d_in[6];
    const float* wcx_w = (const float*)d_in[7];
    const float* wcx_b = (const float*)d_in[8];
    const float* wfh_w = (const float*)d_in[9];
    const float* wih_w = (const float*)d_in[10];
    const float* woh_w = (const float*)d_in[11];
    const float* wch_w = (const float*)d_in[12];
    const float* fco_w = (const float*)d_in[13];
    const float* fco_b = (const float*)d_in[14];
    float* out = (float*)d_out;

    cudaFuncSetAttribute(lstm_rec, cudaFuncAttributeMaxDynamicSharedMemorySize,
                         SMEM_REC);

    init_k<<<1, 1>>>();
    gates_gemm<<<dim3(4 * HDIM / 64, TSTEPS * BATCH / 64), 256>>>(
        x, wfx_w, wix_w, wox_w, wcx_w, wfx_b, wix_b, wox_b, wcx_b);
    lstm_rec<<<NCTA, 256, SMEM_REC>>>(wfh_w, wih_w, woh_w, wch_w);
    out_gemm<<<dim3((CDIM + 63) / 64, TSTEPS * BATCH / 64), 256>>>(
        fco_w, fco_b, out);
}

// round 6
// speedup vs baseline: 6.0215x; 1.1767x over previous
#include <cuda_runtime.h>
#include <math.h>

typedef unsigned long long ull;

#define TSTEPS 512
#define BATCH  64
#define FDIM   256
#define HDIM   1024
#define CDIM   257
#define NCTA   128
#define NJ     8

// lstm_rec dynamic smem layout (bytes)
#define OFF_H0   131072            // after 16384 ull dup-packed weights
#define OFF_H1   163840
#define OFF_RED  196608
#define OFF_MB   229376
#define SMEM_REC 229440

__device__ float g_gx[(size_t)TSTEPS * 4 * BATCH * HDIM];   // [t][g][b][j]
__device__ float g_hs[(size_t)TSTEPS * BATCH * HDIM];       // [t][b][j] natural
__device__ float g_hst[(size_t)TSTEPS * HDIM * BATCH];      // [t][j][b] transposed
__device__ unsigned g_arrive;
__device__ volatile unsigned g_release;

static __device__ __forceinline__ ull pack2(float a, float b) {
    ull r; asm("mov.b64 %0, {%1, %2};" : "=l"(r) : "f"(a), "f"(b)); return r;
}
static __device__ __forceinline__ ull fma2(ull a, ull b, ull c) {
    ull d; asm("fma.rn.f32x2 %0, %1, %2, %3;" : "=l"(d) : "l"(a), "l"(b), "l"(c));
    return d;
}
static __device__ __forceinline__ float2 unpack2(ull a) {
    float2 f; asm("mov.b64 {%0, %1}, %2;" : "=f"(f.x), "=f"(f.y) : "l"(a)); return f;
}
static __device__ __forceinline__ float sigmoid_f(float x) {
    return 1.f / (1.f + __expf(-x));
}
static __device__ __forceinline__ float tanh_f(float x) {
    float e = __expf(2.f * x);
    return 1.f - 2.f / (e + 1.f);
}
static __device__ __forceinline__ unsigned smem_u32(const void* p) {
    return (unsigned)__cvta_generic_to_shared(p);
}
static __device__ __forceinline__ void mbar_init(unsigned a) {
    asm volatile("mbarrier.init.shared.b64 [%0], 1;" :: "r"(a) : "memory");
}
static __device__ __forceinline__ void bulk_ld(unsigned dst, const float* src,
                                               unsigned bytes, unsigned mbar) {
    asm volatile("mbarrier.arrive.expect_tx.shared.b64 _, [%0], %1;"
                 :: "r"(mbar), "r"(bytes) : "memory");
    asm volatile("cp.async.bulk.shared::cluster.global.mbarrier::complete_tx::bytes "
                 "[%0], [%1], %2, [%3];"
                 :: "r"(dst), "l"(src), "r"(bytes), "r"(mbar) : "memory");
}
static __device__ __forceinline__ void mbar_wait(unsigned mbar, unsigned phase) {
    asm volatile(
        "{\n\t.reg .pred P;\n\t"
        "LW_%=:\n\t"
        "mbarrier.try_wait.parity.acquire.cta.shared::cta.b64 P, [%0], %1, 0x989680;\n\t"
        "@P bra LD_%=;\n\t"
        "bra LW_%=;\n\t"
        "LD_%=:\n\t}"
        :: "r"(mbar), "r"(phase) : "memory");
}

// ===========================================================================
// Kernel 1: gates_x = x @ Wx^T + b -> g_gx[t][g][b][j].
// k-pair-major smem (ull[16][66]): rm/rn inner reads are contiguous LDS.128,
// conflict-free. 16 FFMA2 : 4 LDS.128 per k-pair iteration.
// ===========================================================================
__global__ __launch_bounds__(256) void gates_gemm(
    const float* __restrict__ x,
    const float* __restrict__ w0, const float* __restrict__ w1,
    const float* __restrict__ w2, const float* __restrict__ w3,
    const float* __restrict__ b0, const float* __restrict__ b1,
    const float* __restrict__ b2, const float* __restrict__ b3)
{
    __shared__ ull As2[16][66];   // [k-pair][row], +2 pad
    __shared__ ull Bs2[16][66];

    const int tid = threadIdx.x;
    const int n0 = blockIdx.x * 64;
    const int m0 = blockIdx.y * 64;
    const int g  = n0 >> 10;
    const int jb = n0 & 1023;
    const float* W  = (g == 0) ? w0 : (g == 1) ? w1 : (g == 2) ? w2 : w3;
    const float* Bv = (g == 0) ? b0 : (g == 1) ? b1 : (g == 2) ? b2 : b3;
    const int ty = tid >> 4, tx = tid & 15;

    ull acc[4][4];
#pragma unroll
    for (int i = 0; i < 4; i++)
#pragma unroll
        for (int j = 0; j < 4; j++) acc[i][j] = 0ull;

    for (int k0 = 0; k0 < FDIM; k0 += 32) {
#pragma unroll
        for (int i = 0; i < 2; i++) {
            int idx = tid + i * 256;
            int r = idx >> 3, c4 = (idx & 7) * 4;
            float4 av = *(const float4*)(x + (size_t)(m0 + r) * FDIM + k0 + c4);
            As2[(c4 >> 1) + 0][r] = pack2(av.x, av.y);
            As2[(c4 >> 1) + 1][r] = pack2(av.z, av.w);
            float4 bv = *(const float4*)(W + (size_t)(jb + r) * FDIM + k0 + c4);
            Bs2[(c4 >> 1) + 0][r] = pack2(bv.x, bv.y);
            Bs2[(c4 >> 1) + 1][r] = pack2(bv.z, bv.w);
        }
        __syncthreads();
#pragma unroll 4
        for (int kk2 = 0; kk2 < 16; kk2++) {
            ulonglong2 rmA = *(const ulonglong2*)&As2[kk2][ty * 4];
            ulonglong2 rmB = *(const ulonglong2*)&As2[kk2][ty * 4 + 2];
            ulonglong2 rnA = *(const ulonglong2*)&Bs2[kk2][tx * 4];
            ulonglong2 rnB = *(const ulonglong2*)&Bs2[kk2][tx * 4 + 2];
            ull rm[4] = { rmA.x, rmA.y, rmB.x, rmB.y };
            ull rn[4] = { rnA.x, rnA.y, rnB.x, rnB.y };
#pragma unroll
            for (int i = 0; i < 4; i++)
#pragma unroll
                for (int j = 0; j < 4; j++)
                    acc[i][j] = fma2(rm[i], rn[j], acc[i][j]);
        }
        __syncthreads();
    }

    float bj[4];
#pragma unroll
    for (int j = 0; j < 4; j++) bj[j] = Bv[jb + tx * 4 + j];

#pragma unroll
    for (int i = 0; i < 4; i++) {
        int m = m0 + ty * 4 + i;
        int t = m >> 6, b = m & 63;
        float4 o;
        float2 v0 = unpack2(acc[i][0]);
        float2 v1 = unpack2(acc[i][1]);
        float2 v2 = unpack2(acc[i][2]);
        float2 v3 = unpack2(acc[i][3]);
        o.x = v0.x + v0.y + bj[0];
        o.y = v1.x + v1.y + bj[1];
        o.z = v2.x + v2.y + bj[2];
        o.w = v3.x + v3.y + bj[3];
        *(float4*)(g_gx + (((size_t)t * 4 + g) * BATCH + b) * HDIM + jb + tx * 4) = o;
    }
}

// ===========================================================================
// Kernel 2: persistent recurrence (unchanged from R4 — proven).
// ===========================================================================
__global__ __launch_bounds__(256, 1) void lstm_rec(
    const float* __restrict__ wfh, const float* __restrict__ wih,
    const float* __restrict__ woh, const float* __restrict__ wch)
{
    extern __shared__ unsigned char sm[];
    ull*   wp   = (ull*)sm;
    float* hbA  = (float*)(sm + OFF_H0);
    float* hbB  = (float*)(sm + OFF_H1);
    ull*   red  = (ull*)(sm + OFF_RED);
    const unsigned mb0 = smem_u32(sm + OFF_MB), mb1 = mb0 + 8;

    const int tid = threadIdx.x;
    const int bp = tid & 31, ks = (tid >> 5) & 3, jg = tid >> 7;
    const int jq = tid >> 6, bc = tid & 63;
    const int j0 = blockIdx.x * NJ;

    if (tid == 0) {
        mbar_init(mb0); mbar_init(mb1);
        asm volatile("fence.proxy.async.shared::cta;" ::: "memory");
    }
    for (int it = tid; it < 4096; it += 256) {
        int g = it >> 10, rem = it & 1023, jp = rem >> 8, k4 = (rem & 255) * 4;
        const float* W = (g == 0) ? wfh : (g == 1) ? wih : (g == 2) ? woh : wch;
        float4 a = *(const float4*)(W + (size_t)(j0 + 2 * jp)     * HDIM + k4);
        float4 c = *(const float4*)(W + (size_t)(j0 + 2 * jp + 1) * HDIM + k4);
        ull* d = wp + (g * 4 + jp) * HDIM + k4;
        d[0] = pack2(a.x, c.x); d[1] = pack2(a.y, c.y);
        d[2] = pack2(a.z, c.z); d[3] = pack2(a.w, c.w);
    }
    __syncthreads();

    float cc0 = 0.f, cc1 = 0.f;
    unsigned ph0 = 0, ph1 = 0;
    const ull* wbase = wp + jg * 8 * HDIM;

    for (int t = 0; t < TSTEPS; t++) {
        float2 gx[4];
#pragma unroll
        for (int g = 0; g < 4; g++)
            gx[g] = *(const float2*)(g_gx +
                (((size_t)t * 4 + g) * BATCH + bc) * HDIM + j0 + 2 * jq);

        ull acc[16];
#pragma unroll
        for (int s = 0; s < 16; s++) acc[s] = 0ull;

        if (t > 0) {
            const float* hsrc = g_hst + (size_t)(t - 1) * HDIM * BATCH;
            if (tid == 0) {
                bulk_ld(smem_u32(hbA), hsrc,        32768, mb0);
                bulk_ld(smem_u32(hbB), hsrc + 8192, 32768, mb1);
            }
#pragma unroll 1
            for (int ch = 0; ch < 8; ch++) {
                if (ch & 1) { mbar_wait(mb1, ph1); ph1 ^= 1; }
                else        { mbar_wait(mb0, ph0); ph0 ^= 1; }

                const float* hq = ((ch & 1) ? hbB : hbA) + ks * 32 * 64 + 2 * bp;
                const ull*   wk = wbase + ch * 128 + ks * 32;
#pragma unroll 4
                for (int kk = 0; kk < 32; kk += 2) {
                    float2 h0 = *(const float2*)(hq + kk * 64);
                    float2 h1 = *(const float2*)(hq + kk * 64 + 64);
                    ull a00 = pack2(h0.x, h0.x), a01 = pack2(h0.y, h0.y);
                    ull a10 = pack2(h1.x, h1.x), a11 = pack2(h1.y, h1.y);
#pragma unroll
                    for (int s = 0; s < 8; s++) {
                        ulonglong2 w = *(const ulonglong2*)(wk + s * HDIM + kk);
                        acc[2*s]   = fma2(a00, w.x, acc[2*s]);
                        acc[2*s]   = fma2(a10, w.y, acc[2*s]);
                        acc[2*s+1] = fma2(a01, w.x, acc[2*s+1]);
                        acc[2*s+1] = fma2(a11, w.y, acc[2*s+1]);
                    }
                }
                __syncthreads();
                if (tid == 0 && ch < 6)
                    bulk_ld(smem_u32((ch & 1) ? hbB : hbA),
                            hsrc + (ch + 2) * 8192, 32768, (ch & 1) ? mb1 : mb0);
            }
        }

#pragma unroll
        for (int s = 0; s < 8; s++) {
            int gjp = jg * 8 + s;
            *(ulonglong2*)(red + (gjp * 4 + ks) * 64 + 2 * bp) =
                make_ulonglong2(acc[2*s], acc[2*s+1]);
        }
        __syncthreads();

        float z0[4], z1[4];
#pragma unroll
        for (int g = 0; g < 4; g++) {
            float sx = gx[g].x, sy = gx[g].y;
#pragma unroll
            for (int q = 0; q < 4; q++) {
                float2 p = unpack2(red[((g * 4 + jq) * 4 + q) * 64 + bc]);
                sx += p.x; sy += p.y;
            }
            z0[g] = sx; z1[g] = sy;
        }
        float cp0 = (t == 0) ? 0.f : cc0;
        float cp1 = (t == 0) ? 0.f : cc1;
        cc0 = sigmoid_f(z0[1]) * tanh_f(z0[3]) + sigmoid_f(z0[0]) * cp0;
        cc1 = sigmoid_f(z1[1]) * tanh_f(z1[3]) + sigmoid_f(z1[0]) * cp1;
        float hv0 = sigmoid_f(z0[2]) * tanh_f(cc0);
        float hv1 = sigmoid_f(z1[2]) * tanh_f(cc1);

        *(float2*)(g_hs + ((size_t)t * BATCH + bc) * HDIM + j0 + 2 * jq) =
            make_float2(hv0, hv1);
        size_t tb = ((size_t)t * HDIM + j0 + 2 * jq) * BATCH + bc;
        g_hst[tb]         = hv0;
        g_hst[tb + BATCH] = hv1;

        if (t < TSTEPS - 1) {
            __threadfence();
            __syncthreads();
            if (tid == 0) {
                unsigned prev = atomicAdd(&g_arrive, 1u);
                unsigned target = (unsigned)(t + 1) * NCTA;
                if (prev == target - 1) {
                    g_release = (unsigned)(t + 1);
                } else {
                    while (g_release < (unsigned)(t + 1)) { }
                }
                __threadfence();
            }
            __syncthreads();
        }
    }
}

// ===========================================================================
// Kernel 3: out = hs @ fco^T + b — same conflict-free k-pair layout.
// ===========================================================================
__global__ __launch_bounds__(256) void out_gemm(
    const float* __restrict__ fw, const float* __restrict__ fb,
    float* __restrict__ out)
{
    __shared__ ull As2[16][66];
    __shared__ ull Bs2[16][66];

    const int tid = threadIdx.x;
    const int n0 = blockIdx.x * 64;
    const int m0 = blockIdx.y * 64;
    const int ty = tid >> 4, tx = tid & 15;

    ull acc[4][4];
#pragma unroll
    for (int i = 0; i < 4; i++)
#pragma unroll
        for (int j = 0; j < 4; j++) acc[i][j] = 0ull;

    for (int k0 = 0; k0 < HDIM; k0 += 32) {
#pragma unroll
        for (int i = 0; i < 2; i++) {
            int idx = tid + i * 256;
            int r = idx >> 3, c4 = (idx & 7) * 4;
            float4 av = *(const float4*)(g_hs + (size_t)(m0 + r) * HDIM + k0 + c4);
            As2[(c4 >> 1) + 0][r] = pack2(av.x, av.y);
            As2[(c4 >> 1) + 1][r] = pack2(av.z, av.w);
            int jr = n0 + r;
            float4 bv = make_float4(0.f, 0.f, 0.f, 0.f);
            if (jr < CDIM)
                bv = *(const float4*)(fw + (size_t)jr * HDIM + k0 + c4);
            Bs2[(c4 >> 1) + 0][r] = pack2(bv.x, bv.y);
            Bs2[(c4 >> 1) + 1][r] = pack2(bv.z, bv.w);
        }
        __syncthreads();
#pragma unroll 4
        for (int kk2 = 0; kk2 < 16; kk2++) {
            ulonglong2 rmA = *(const ulonglong2*)&As2[kk2][ty * 4];
            ulonglong2 rmB = *(const ulonglong2*)&As2[kk2][ty * 4 + 2];
            ulonglong2 rnA = *(const ulonglong2*)&Bs2[kk2][tx * 4];
            ulonglong2 rnB = *(const ulonglong2*)&Bs2[kk2][tx * 4 + 2];
            ull rm[4] = { rmA.x, rmA.y, rmB.x, rmB.y };
            ull rn[4] = { rnA.x, rnA.y, rnB.x, rnB.y };
#pragma unroll
            for (int i = 0; i < 4; i++)
#pragma unroll
                for (int j = 0; j < 4; j++)
                    acc[i][j] = fma2(rm[i], rn[j], acc[i][j]);
        }
        __syncthreads();
    }

#pragma unroll
    for (int i = 0; i < 4; i++) {
        int m = m0 + ty * 4 + i;
#pragma unroll
        for (int j = 0; j < 4; j++) {
            int n = n0 + tx * 4 + j;
            if (n < CDIM) {
                float2 v = unpack2(acc[i][j]);
                out[(size_t)m * CDIM + n] = v.x + v.y + fb[n];
            }
        }
    }
}

__global__ void init_k() { g_arrive = 0; g_release = 0; }

extern "C" void kernel_launch(void* const* d_in, const int* in_sizes, int n_in,
                              void* d_out, int out_size)
{
    const float* x     = (const float*)d_in[0];
    const float* wfx_w = (const float*)d_in[1];
    const float* wfx_b = (const float*)d_in[2];
    const float* wix_w = (const float*)d_in[3];
    const float* wix_b = (const float*)d_in[4];
    const float* wox_w = (const float*)d_in[5];
    const float* wox_b = (const float*)d_in[6];
    const float* wcx_w = (const float*)d_in[7];
    const float* wcx_b = (const float*)d_in[8];
    const float* wfh_w = (const float*)d_in[9];
    const float* wih_w = (const float*)d_in[10];
    const float* woh_w = (const float*)d_in[11];
    const float* wch_w = (const float*)d_in[12];
    const float* fco_w = (const float*)d_in[13];
    const float* fco_b = (const float*)d_in[14];
    float* out = (float*)d_out;

    cudaFuncSetAttribute(lstm_rec, cudaFuncAttributeMaxDynamicSharedMemorySize,
                         SMEM_REC);

    init_k<<<1, 1>>>();
    gates_gemm<<<dim3(4 * HDIM / 64, TSTEPS * BATCH / 64), 256>>>(
        x, wfx_w, wix_w, wox_w, wcx_w, wfx_b, wix_b, wox_b, wcx_b);
    lstm_rec<<<NCTA, 256, SMEM_REC>>>(wfh_w, wih_w, woh_w, wch_w);
    out_gemm<<<dim3((CDIM + 63) / 64, TSTEPS * BATCH / 64), 256>>>(
        fco_w, fco_b, out);
}

// round 7
// speedup vs baseline: 6.0607x; 1.0065x over previous
#include <cuda_runtime.h>
#include <math.h>

typedef unsigned long long ull;

#define TSTEPS 512
#define BATCH  64
#define FDIM   256
#define HDIM   1024
#define CDIM   257
#define NCTA   128
#define NJ     8
#define NTHR   512

// lstm_rec dynamic smem layout (bytes)
#define OFF_WX   131072            // after 16384 ull dup-packed h-weights
#define OFF_H0   163840            // after 4096 ull dup-packed x-weights
#define OFF_H1   196608
#define OFF_RED  163840            // overlays hbA (safe: see sync analysis)
#define OFF_MB   229376
#define SMEM_REC 229392

__device__ float g_xt[(size_t)TSTEPS * FDIM * BATCH];       // [t][f][b]
__device__ float g_hst[(size_t)TSTEPS * HDIM * BATCH];      // [t][j][b]
__device__ unsigned g_cnt[8];
__device__ unsigned g_root;
__device__ volatile unsigned g_release;

static __device__ __forceinline__ ull pack2(float a, float b) {
    ull r; asm("mov.b64 %0, {%1, %2};" : "=l"(r) : "f"(a), "f"(b)); return r;
}
static __device__ __forceinline__ ull fma2(ull a, ull b, ull c) {
    ull d; asm("fma.rn.f32x2 %0, %1, %2, %3;" : "=l"(d) : "l"(a), "l"(b), "l"(c));
    return d;
}
static __device__ __forceinline__ float2 unpack2(ull a) {
    float2 f; asm("mov.b64 {%0, %1}, %2;" : "=f"(f.x), "=f"(f.y) : "l"(a)); return f;
}
static __device__ __forceinline__ float sigmoid_f(float x) {
    return 1.f / (1.f + __expf(-x));
}
static __device__ __forceinline__ float tanh_f(float x) {
    float e = __expf(2.f * x);
    return 1.f - 2.f / (e + 1.f);
}
static __device__ __forceinline__ unsigned smem_u32(const void* p) {
    return (unsigned)__cvta_generic_to_shared(p);
}
static __device__ __forceinline__ void mbar_init(unsigned a) {
    asm volatile("mbarrier.init.shared.b64 [%0], 1;" :: "r"(a) : "memory");
}
static __device__ __forceinline__ void bulk_ld(unsigned dst, const float* src,
                                               unsigned bytes, unsigned mbar) {
    asm volatile("mbarrier.arrive.expect_tx.shared.b64 _, [%0], %1;"
                 :: "r"(mbar), "r"(bytes) : "memory");
    asm volatile("cp.async.bulk.shared::cluster.global.mbarrier::complete_tx::bytes "
                 "[%0], [%1], %2, [%3];"
                 :: "r"(dst), "l"(src), "r"(bytes), "r"(mbar) : "memory");
}
static __device__ __forceinline__ void mbar_wait(unsigned mbar, unsigned phase) {
    asm volatile(
        "{\n\t.reg .pred P;\n\t"
        "LW_%=:\n\t"
        "mbarrier.try_wait.parity.acquire.cta.shared::cta.b64 P, [%0], %1, 0x989680;\n\t"
        "@P bra LD_%=;\n\t"
        "bra LW_%=;\n\t"
        "LD_%=:\n\t}"
        :: "r"(mbar), "r"(phase) : "memory");
}

// ===========================================================================
// Kernel 0: transpose x[t][b][f] -> g_xt[t][f][b]
// ===========================================================================
__global__ __launch_bounds__(256) void xpose(const float* __restrict__ x)
{
    __shared__ float tile[32][33];
    const int t  = blockIdx.z;
    const int f0 = blockIdx.x * 32;
    const int b0 = blockIdx.y * 32;
    const int tx = threadIdx.x, ty = threadIdx.y;

    const float* src = x + ((size_t)t * BATCH + b0) * FDIM + f0;
#pragma unroll
    for (int i = ty; i < 32; i += 8)
        tile[i][tx] = src[(size_t)i * FDIM + tx];     // tile[b][f]
    __syncthreads();
    float* dst = g_xt + ((size_t)t * FDIM + f0) * BATCH + b0;
#pragma unroll
    for (int i = ty; i < 32; i += 8)
        dst[(size_t)i * BATCH + tx] = tile[tx][i];    // xt[f][b]
}

// ===========================================================================
// Kernel 1: persistent recurrence with fused input projection.
// 128 CTAs x 512 thr. thread: bp=tid&31 (b-pair), ks=(tid>>5)&3 (k quarter),
// jg=tid>>7 (gate). 8 f32x2 accs = 4 j-pairs x 2 b. Chunks 0-1: x[t] (no
// barrier dependency, hides h copy latency); 2-9: h(t-1). Weight LDS.128
// warp-uniform broadcast; h LDS.64 contiguous. Two-level grid barrier.
// ===========================================================================
template <int STRIDE>
static __device__ __forceinline__ void chunk_fma(
    const float* hq, const ull* wk, ull* acc)
{
#pragma unroll 4
    for (int kk = 0; kk < 32; kk += 2) {
        float2 h0 = *(const float2*)(hq + kk * 64);
        float2 h1 = *(const float2*)(hq + kk * 64 + 64);
        ull a00 = pack2(h0.x, h0.x), a01 = pack2(h0.y, h0.y);
        ull a10 = pack2(h1.x, h1.x), a11 = pack2(h1.y, h1.y);
#pragma unroll
        for (int s = 0; s < 4; s++) {
            ulonglong2 w = *(const ulonglong2*)(wk + s * STRIDE + kk);
            acc[2*s]   = fma2(a00, w.x, acc[2*s]);
            acc[2*s]   = fma2(a10, w.y, acc[2*s]);
            acc[2*s+1] = fma2(a01, w.x, acc[2*s+1]);
            acc[2*s+1] = fma2(a11, w.y, acc[2*s+1]);
        }
    }
}

__global__ __launch_bounds__(NTHR, 1) void lstm_rec(
    const float* __restrict__ wfh, const float* __restrict__ wih,
    const float* __restrict__ woh, const float* __restrict__ wch,
    const float* __restrict__ wfx, const float* __restrict__ wix,
    const float* __restrict__ wox, const float* __restrict__ wcx,
    const float* __restrict__ bf,  const float* __restrict__ bi,
    const float* __restrict__ bo,  const float* __restrict__ bcv)
{
    extern __shared__ unsigned char sm[];
    ull*   wp   = (ull*)sm;                    // h-weights dup-packed
    ull*   wxp  = (ull*)(sm + OFF_WX);         // x-weights dup-packed
    float* hbA  = (float*)(sm + OFF_H0);
    float* hbB  = (float*)(sm + OFF_H1);
    ull*   red  = (ull*)(sm + OFF_RED);        // overlays hbA
    const unsigned mb0 = smem_u32(sm + OFF_MB), mb1 = mb0 + 8;

    const int tid = threadIdx.x;
    const int bp = tid & 31, ks = (tid >> 5) & 3, jg = tid >> 7;
    const int jq = tid >> 6, bc = tid & 63;    // consumer mapping (tid<256)
    const int j0 = blockIdx.x * NJ;

    if (tid == 0) {
        mbar_init(mb0); mbar_init(mb1);
        asm volatile("fence.proxy.async.shared::cta;" ::: "memory");
    }
    // h-weight slice: wp[(g*4+jp)*HDIM + k] = (w[j0+2jp][k], w[j0+2jp+1][k])
    for (int it = tid; it < 4096; it += NTHR) {
        int g = it >> 10, rem = it & 1023, jp = rem >> 8, k4 = (rem & 255) * 4;
        const float* W = (g == 0) ? wfh : (g == 1) ? wih : (g == 2) ? woh : wch;
        float4 a = *(const float4*)(W + (size_t)(j0 + 2 * jp)     * HDIM + k4);
        float4 c = *(const float4*)(W + (size_t)(j0 + 2 * jp + 1) * HDIM + k4);
        ull* d = wp + (g * 4 + jp) * HDIM + k4;
        d[0] = pack2(a.x, c.x); d[1] = pack2(a.y, c.y);
        d[2] = pack2(a.z, c.z); d[3] = pack2(a.w, c.w);
    }
    // x-weight slice: wxp[(g*4+jp)*FDIM + k]
    for (int it = tid; it < 1024; it += NTHR) {
        int g = it >> 8, rem = it & 255, jp = rem >> 6, k4 = (rem & 63) * 4;
        const float* W = (g == 0) ? wfx : (g == 1) ? wix : (g == 2) ? wox : wcx;
        float4 a = *(const float4*)(W + (size_t)(j0 + 2 * jp)     * FDIM + k4);
        float4 c = *(const float4*)(W + (size_t)(j0 + 2 * jp + 1) * FDIM + k4);
        ull* d = wxp + (g * 4 + jp) * FDIM + k4;
        d[0] = pack2(a.x, c.x); d[1] = pack2(a.y, c.y);
        d[2] = pack2(a.z, c.z); d[3] = pack2(a.w, c.w);
    }
    __syncthreads();

    // consumer biases for (g, j0+2jq, j0+2jq+1)
    float2 bias[4];
    if (tid < 256) {
        bias[0] = *(const float2*)(bf  + j0 + 2 * jq);
        bias[1] = *(const float2*)(bi  + j0 + 2 * jq);
        bias[2] = *(const float2*)(bo  + j0 + 2 * jq);
        bias[3] = *(const float2*)(bcv + j0 + 2 * jq);
    }

    float cc0 = 0.f, cc1 = 0.f;
    unsigned ph0 = 0, ph1 = 0;
    const ull* wh_base = wp  + jg * 4 * HDIM + ks * 32;
    const ull* wx_base = wxp + jg * 4 * FDIM + ks * 32;
    const float* hqoff0 = (const float*)0;     // silence unused warnings

    for (int t = 0; t < TSTEPS; t++) {
        ull acc[8];
#pragma unroll
        for (int s = 0; s < 8; s++) acc[s] = 0ull;

        const float* xsrc = g_xt + (size_t)t * FDIM * BATCH;
        const float* hsrc = g_hst + (size_t)(t - 1) * HDIM * BATCH;
        const int nch = (t > 0) ? 10 : 2;

        if (tid == 0) {
            bulk_ld(smem_u32(hbA), xsrc,        32768, mb0);
            bulk_ld(smem_u32(hbB), xsrc + 8192, 32768, mb1);
        }
#pragma unroll 1
        for (int ch = 0; ch < nch; ch++) {
            if (ch & 1) { mbar_wait(mb1, ph1); ph1 ^= 1; }
            else        { mbar_wait(mb0, ph0); ph0 ^= 1; }

            const float* hq = ((ch & 1) ? hbB : hbA) + ks * 32 * 64 + 2 * bp;
            if (ch < 2) chunk_fma<FDIM>(hq, wx_base + ch * 128, acc);
            else        chunk_fma<HDIM>(hq, wh_base + (ch - 2) * 128, acc);
            __syncthreads();
            if (tid == 0 && ch + 2 < nch)
                bulk_ld(smem_u32((ch & 1) ? hbB : hbA),
                        hsrc + (size_t)ch * 8192, 32768, (ch & 1) ? mb1 : mb0);
        }

        // partials -> red (overlays hbA; all copies drained, all chunks synced)
#pragma unroll
        for (int s = 0; s < 4; s++) {
            int gjp = jg * 4 + s;
            *(ulonglong2*)(red + (gjp * 4 + ks) * 64 + 2 * bp) =
                make_ulonglong2(acc[2*s], acc[2*s+1]);
        }
        __syncthreads();

        if (tid < 256) {
            float z0[4], z1[4];
#pragma unroll
            for (int g = 0; g < 4; g++) {
                float sx = bias[g].x, sy = bias[g].y;
#pragma unroll
                for (int q = 0; q < 4; q++) {
                    float2 p = unpack2(red[((g * 4 + jq) * 4 + q) * 64 + bc]);
                    sx += p.x; sy += p.y;
                }
                z0[g] = sx; z1[g] = sy;
            }
            float cp0 = (t == 0) ? 0.f : cc0;
            float cp1 = (t == 0) ? 0.f : cc1;
            cc0 = sigmoid_f(z0[1]) * tanh_f(z0[3]) + sigmoid_f(z0[0]) * cp0;
            cc1 = sigmoid_f(z1[1]) * tanh_f(z1[3]) + sigmoid_f(z1[0]) * cp1;
            float hv0 = sigmoid_f(z0[2]) * tanh_f(cc0);
            float hv1 = sigmoid_f(z1[2]) * tanh_f(cc1);

            size_t tb = ((size_t)t * HDIM + j0 + 2 * jq) * BATCH + bc;
            g_hst[tb]         = hv0;
            g_hst[tb + BATCH] = hv1;
        }

        // two-level grid barrier
        if (t < TSTEPS - 1) {
            __threadfence();
            __syncthreads();
            if (tid == 0) {
                int grp = blockIdx.x >> 4;
                unsigned prev = atomicAdd(&g_cnt[grp], 1u);
                if (prev == (unsigned)(t + 1) * 16 - 1) {
                    unsigned pr = atomicAdd(&g_root, 1u);
                    if (pr == (unsigned)(t + 1) * 8 - 1)
                        g_release = (unsigned)(t + 1);
                }
                while (g_release < (unsigned)(t + 1)) { }
                __threadfence();
            }
            __syncthreads();
        }
    }
    (void)hqoff0;
}

// ===========================================================================
// Kernel 2: out = hs @ fco^T + b. A read from transposed g_hst with
// pack-transpose loader; conflict-free k-pair inner loop.
// ===========================================================================
__global__ __launch_bounds__(256) void out_gemm(
    const float* __restrict__ fw, const float* __restrict__ fb,
    float* __restrict__ out)
{
    __shared__ ull As2[16][66];
    __shared__ ull Bs2[16][66];

    const int tid = threadIdx.x;
    const int n0 = blockIdx.x * 64;
    const int m0 = blockIdx.y * 64;
    const int t  = m0 >> 6;            // 64 rows per timestep exactly
    const int ty = tid >> 4, tx = tid & 15;
    const int kpa = tid >> 4;          // A loader: k-pair 0..15
    const int b4  = (tid & 15) * 4;    // A loader: b 0..60

    ull acc[4][4];
#pragma unroll
    for (int i = 0; i < 4; i++)
#pragma unroll
        for (int j = 0; j < 4; j++) acc[i][j] = 0ull;

    for (int k0 = 0; k0 < HDIM; k0 += 32) {
        // A: As2[kp][b] = (h[t][k0+2kp][b], h[t][k0+2kp+1][b])
        {
            const float* base = g_hst + ((size_t)t * HDIM + k0 + 2 * kpa) * BATCH + b4;
            float4 ev = *(const float4*)base;
            float4 od = *(const float4*)(base + BATCH);
            As2[kpa][b4 + 0] = pack2(ev.x, od.x);
            As2[kpa][b4 + 1] = pack2(ev.y, od.y);
            As2[kpa][b4 + 2] = pack2(ev.z, od.z);
            As2[kpa][b4 + 3] = pack2(ev.w, od.w);
        }
        // B: fco_w rows (guarded)
#pragma unroll
        for (int i = 0; i < 2; i++) {
            int idx = tid + i * 256;
            int r = idx >> 3, c4 = (idx & 7) * 4;
            int jr = n0 + r;
            float4 bv = make_float4(0.f, 0.f, 0.f, 0.f);
            if (jr < CDIM)
                bv = *(const float4*)(fw + (size_t)jr * HDIM + k0 + c4);
            Bs2[(c4 >> 1) + 0][r] = pack2(bv.x, bv.y);
            Bs2[(c4 >> 1) + 1][r] = pack2(bv.z, bv.w);
        }
        __syncthreads();
#pragma unroll 4
        for (int kk2 = 0; kk2 < 16; kk2++) {
            ulonglong2 rmA = *(const ulonglong2*)&As2[kk2][ty * 4];
            ulonglong2 rmB = *(const ulonglong2*)&As2[kk2][ty * 4 + 2];
            ulonglong2 rnA = *(const ulonglong2*)&Bs2[kk2][tx * 4];
            ulonglong2 rnB = *(const ulonglong2*)&Bs2[kk2][tx * 4 + 2];
            ull rm[4] = { rmA.x, rmA.y, rmB.x, rmB.y };
            ull rn[4] = { rnA.x, rnA.y, rnB.x, rnB.y };
#pragma unroll
            for (int i = 0; i < 4; i++)
#pragma unroll
                for (int j = 0; j < 4; j++)
                    acc[i][j] = fma2(rm[i], rn[j], acc[i][j]);
        }
        __syncthreads();
    }

#pragma unroll
    for (int i = 0; i < 4; i++) {
        int m = m0 + ty * 4 + i;
#pragma unroll
        for (int j = 0; j < 4; j++) {
            int n = n0 + tx * 4 + j;
            if (n < CDIM) {
                float2 v = unpack2(acc[i][j]);
                out[(size_t)m * CDIM + n] = v.x + v.y + fb[n];
            }
        }
    }
}

__global__ void init_k() {
    g_root = 0; g_release = 0;
    for (int i = 0; i < 8; i++) g_cnt[i] = 0;
}

extern "C" void kernel_launch(void* const* d_in, const int* in_sizes, int n_in,
                              void* d_out, int out_size)
{
    const float* x     = (const float*)d_in[0];
    const float* wfx_w = (const float*)d_in[1];
    const float* wfx_b = (const float*)d_in[2];
    const float* wix_w = (const float*)d_in[3];
    const float* wix_b = (const float*)d_in[4];
    const float* wox_w = (const float*)d_in[5];
    const float* wox_b = (const float*)d_in[6];
    const float* wcx_w = (const float*)d_in[7];
    const float* wcx_b = (const float*)d_in[8];
    const float* wfh_w = (const float*)d_in[9];
    const float* wih_w = (const float*)d_in[10];
    const float* woh_w = (const float*)d_in[11];
    const float* wch_w = (const float*)d_in[12];
    const float* fco_w = (const float*)d_in[13];
    const float* fco_b = (const float*)d_in[14];
    float* out = (float*)d_out;

    cudaFuncSetAttribute(lstm_rec, cudaFuncAttributeMaxDynamicSharedMemorySize,
                         SMEM_REC);

    init_k<<<1, 1>>>();
    xpose<<<dim3(FDIM / 32, BATCH / 32, TSTEPS), dim3(32, 8)>>>(x);
    lstm_rec<<<NCTA, NTHR, SMEM_REC>>>(
        wfh_w, wih_w, woh_w, wch_w,
        wfx_w, wix_w, wox_w, wcx_w,
        wfx_b, wix_b, wox_b, wcx_b);
    out_gemm<<<dim3((CDIM + 63) / 64, TSTEPS * BATCH / 64), 256>>>(
        fco_w, fco_b, out);
}

// round 11
// speedup vs baseline: 10.2625x; 1.6933x over previous
#include <cuda_runtime.h>
#include <cuda_bf16.h>
#include <math.h>

typedef unsigned long long ull;

#define TSTEPS 512
#define BATCH  64
#define FDIM   256
#define HDIM   1024
#define CDIM   257
#define NCTA   128

// lstm_rec smem layout (bytes)
#define OFF_WHI  0          // W hi: 32 rows x 160 16B-units (80KB), XOR-swizzled
#define OFF_WLO  81920      // W lo (80KB)
#define OFF_A0   163840     // act buf 0: hi 16KB + lo 16KB
#define OFF_A1   196608     // act buf 1
#define OFF_MB   229376     // 2 mbarriers
#define OFF_BIAS 229392     // 32 floats
#define SMEM_REC 229520
#define WPITCH   2560       // W row pitch bytes (1280 k x 2B)

// ---------------- global scratch ----------------
__device__ __align__(128) unsigned char g_xh[(size_t)TSTEPS * 2 * 16384];
__device__ __align__(128) unsigned char g_xl[(size_t)TSTEPS * 2 * 16384];
__device__ __align__(128) unsigned char g_hh[(size_t)TSTEPS * 8 * 16384];
__device__ __align__(128) unsigned char g_hl[(size_t)TSTEPS * 8 * 16384];
__device__ float g_hst[(size_t)TSTEPS * HDIM * BATCH];   // [t][j][b] fp32
__device__ unsigned g_cnt[8];
__device__ unsigned g_root;
__device__ volatile unsigned g_release;

// ---------------- helpers ----------------
static __device__ __forceinline__ ull pack2(float a, float b) {
    ull r; asm("mov.b64 %0, {%1, %2};" : "=l"(r) : "f"(a), "f"(b)); return r;
}
static __device__ __forceinline__ ull fma2(ull a, ull b, ull c) {
    ull d; asm("fma.rn.f32x2 %0, %1, %2, %3;" : "=l"(d) : "l"(a), "l"(b), "l"(c));
    return d;
}
static __device__ __forceinline__ float2 unpack2(ull a) {
    float2 f; asm("mov.b64 {%0, %1}, %2;" : "=f"(f.x), "=f"(f.y) : "l"(a)); return f;
}
static __device__ __forceinline__ float sigmoid_f(float x) {
    return 1.f / (1.f + __expf(-x));
}
static __device__ __forceinline__ float tanh_f(float x) {
    float e = __expf(2.f * x);
    return 1.f - 2.f / (e + 1.f);
}
static __device__ __forceinline__ unsigned smem_u32(const void* p) {
    return (unsigned)__cvta_generic_to_shared(p);
}
static __device__ __forceinline__ void mbar_init(unsigned a) {
    asm volatile("mbarrier.init.shared.b64 [%0], 1;" :: "r"(a) : "memory");
}
static __device__ __forceinline__ void expect_tx(unsigned mbar, unsigned bytes) {
    asm volatile("mbarrier.arrive.expect_tx.shared.b64 _, [%0], %1;"
                 :: "r"(mbar), "r"(bytes) : "memory");
}
static __device__ __forceinline__ void bulk_cp(unsigned dst, const void* src,
                                               unsigned bytes, unsigned mbar) {
    asm volatile("cp.async.bulk.shared::cluster.global.mbarrier::complete_tx::bytes "
                 "[%0], [%1], %2, [%3];"
                 :: "r"(dst), "l"(src), "r"(bytes), "r"(mbar) : "memory");
}
static __device__ __forceinline__ void mbar_wait(unsigned mbar, unsigned phase) {
    asm volatile(
        "{\n\t.reg .pred P;\n\t"
        "LW_%=:\n\t"
        "mbarrier.try_wait.parity.acquire.cta.shared::cta.b64 P, [%0], %1, 0x989680;\n\t"
        "@P bra LD_%=;\n\t"
        "bra LW_%=;\n\t"
        "LD_%=:\n\t}"
        :: "r"(mbar), "r"(phase) : "memory");
}
static __device__ __forceinline__ void ldsm4(unsigned* r, unsigned addr) {
    asm volatile("ldmatrix.sync.aligned.m8n8.x4.shared.b16 {%0,%1,%2,%3}, [%4];"
                 : "=r"(r[0]), "=r"(r[1]), "=r"(r[2]), "=r"(r[3]) : "r"(addr));
}
static __device__ __forceinline__ void ldsm4t(unsigned* r, unsigned addr) {
    asm volatile("ldmatrix.sync.aligned.m8n8.x4.trans.shared.b16 {%0,%1,%2,%3}, [%4];"
                 : "=r"(r[0]), "=r"(r[1]), "=r"(r[2]), "=r"(r[3]) : "r"(addr));
}
static __device__ __forceinline__ void mma16816(float* c, const unsigned* a,
                                                unsigned b0, unsigned b1) {
    asm volatile(
        "mma.sync.aligned.m16n8k16.row.col.f32.bf16.bf16.f32 "
        "{%0,%1,%2,%3},{%4,%5,%6,%7},{%8,%9},{%0,%1,%2,%3};"
        : "+f"(c[0]), "+f"(c[1]), "+f"(c[2]), "+f"(c[3])
        : "r"(a[0]), "r"(a[1]), "r"(a[2]), "r"(a[3]), "r"(b0), "r"(b1));
}
static __device__ __forceinline__ void split_bf(float v, unsigned short& hi_us,
                                                unsigned short& lo_us) {
    __nv_bfloat16 h = __float2bfloat16(v);
    float hf = __bfloat162float(h);
    __nv_bfloat16 l = __float2bfloat16(v - hf);
    unsigned short hu, lu;
    memcpy(&hu, &h, 2); memcpy(&lu, &l, 2);
    hi_us = hu; lo_us = lu;
}

// ===========================================================================
// Kernel 0: x[t][b][f] fp32 -> swizzled bf16 hi/lo act tiles [t][2ch][128k x 64b]
// ===========================================================================
__global__ __launch_bounds__(256) void xsplit(const float* __restrict__ x)
{
    __shared__ float sx[64][129];
    const int t = blockIdx.x;
    for (int half = 0; half < 2; half++) {
        for (int i = threadIdx.x; i < 64 * 128; i += 256) {
            int b = i >> 7, f = i & 127;
            sx[b][f] = x[((size_t)t * BATCH + b) * FDIM + half * 128 + f];
        }
        __syncthreads();
        if (threadIdx.x < 128) {
            int f = threadIdx.x;
            size_t base = ((size_t)t * 2 + half) * 16384 + (size_t)f * 128;
            for (int b8 = 0; b8 < 8; b8++) {
                unsigned short hu[8], lu[8];
#pragma unroll
                for (int e = 0; e < 8; e++)
                    split_bf(sx[b8 * 8 + e][f], hu[e], lu[e]);
                uint4 hv, lv;
                hv.x = ((unsigned)hu[1] << 16) | hu[0];
                hv.y = ((unsigned)hu[3] << 16) | hu[2];
                hv.z = ((unsigned)hu[5] << 16) | hu[4];
                hv.w = ((unsigned)hu[7] << 16) | hu[6];
                lv.x = ((unsigned)lu[1] << 16) | lu[0];
                lv.y = ((unsigned)lu[3] << 16) | lu[2];
                lv.z = ((unsigned)lu[5] << 16) | lu[4];
                lv.w = ((unsigned)lu[7] << 16) | lu[6];
                unsigned us = (unsigned)(b8 ^ (f & 7));
                *(uint4*)(g_xh + base + us * 16) = hv;
                *(uint4*)(g_xl + base + us * 16) = lv;
            }
        }
        __syncthreads();
    }
}

// ===========================================================================
// Kernel 1: persistent mma.sync (bf16x3) recurrence.
// D[32j x 64b] = W[32 x 1280] * Act[1280 x 64], K = [x 0..255 | h 256..1279].
// 8 warps: jt = wid>>2 (j16 tile), bt = wid&3 (b16 tile); warp owns full K.
// ===========================================================================
__global__ __launch_bounds__(256, 1) void lstm_rec(
    const float* __restrict__ wfh, const float* __restrict__ wih,
    const float* __restrict__ woh, const float* __restrict__ wch,
    const float* __restrict__ wfx, const float* __restrict__ wix,
    const float* __restrict__ wox, const float* __restrict__ wcx,
    const float* __restrict__ bf,  const float* __restrict__ bi,
    const float* __restrict__ bo,  const float* __restrict__ bcv)
{
    extern __shared__ unsigned char sm[];
    const unsigned s0 = smem_u32(sm);
    const unsigned sA = s0 + OFF_A0;
    const unsigned mbd0 = s0 + OFF_MB, mbd1 = s0 + OFF_MB + 8;
    float* biasSm = (float*)(sm + OFF_BIAS);
    float* Dx = (float*)(sm + OFF_A0);           // overlay on act buf 0

    const int tid = threadIdx.x;
    const int j0 = blockIdx.x * 8;
    const float* WH[4] = {wfh, wih, woh, wch};
    const float* WX[4] = {wfx, wix, wox, wcx};
    const float* BS[4] = {bf, bi, bo, bcv};

    if (tid == 0) { mbar_init(mbd0); mbar_init(mbd1); }
    if (tid < 32) biasSm[tid] = BS[tid >> 3][j0 + (tid & 7)];

    // ---- weights: 32 rows (g*8+jl) x 1280 k, bf16 hi/lo, unit-swizzled ----
    for (int it = tid; it < 32 * 160; it += 256) {
        int n = it / 160, u = it % 160, k = u * 8;
        int g = n >> 3, jl = n & 7;
        const float* src = (k < 256)
            ? (WX[g] + (size_t)(j0 + jl) * FDIM + k)
            : (WH[g] + (size_t)(j0 + jl) * HDIM + (k - 256));
        float4 v0 = *(const float4*)src;
        float4 v1 = *(const float4*)(src + 4);
        float f[8] = {v0.x, v0.y, v0.z, v0.w, v1.x, v1.y, v1.z, v1.w};
        unsigned short hu[8], lu[8];
#pragma unroll
        for (int e = 0; e < 8; e++) split_bf(f[e], hu[e], lu[e]);
        uint4 hv, lv;
        hv.x = ((unsigned)hu[1] << 16) | hu[0]; hv.y = ((unsigned)hu[3] << 16) | hu[2];
        hv.z = ((unsigned)hu[5] << 16) | hu[4]; hv.w = ((unsigned)hu[7] << 16) | hu[6];
        lv.x = ((unsigned)lu[1] << 16) | lu[0]; lv.y = ((unsigned)lu[3] << 16) | lu[2];
        lv.z = ((unsigned)lu[5] << 16) | lu[4]; lv.w = ((unsigned)lu[7] << 16) | lu[6];
        unsigned off = (unsigned)n * WPITCH + (unsigned)(u ^ (n & 7)) * 16;
        *(uint4*)(sm + OFF_WHI + off) = hv;
        *(uint4*)(sm + OFF_WLO + off) = lv;
    }
    __syncthreads();

    // ---- per-lane fragment addressing constants ----
    const int l = tid & 31, wid = tid >> 5;
    const int jt = wid >> 2, bt = wid & 3;
    const int mi = l >> 3, r = l & 7;
    const int jloc = jt * 16 + (mi & 1) * 8 + r;
    const unsigned rowAhi = s0 + OFF_WHI + (unsigned)jloc * WPITCH;
    const unsigned rowAlo = s0 + OFF_WLO + (unsigned)jloc * WPITCH;
    const unsigned kb = (unsigned)(mi >> 1);
    const unsigned colB = ((unsigned)((bt * 2 + (mi >> 1)) ^ r)) << 4;
    const int krB = (mi & 1) * 8 + r;

    float cst[8];
#pragma unroll
    for (int jl = 0; jl < 8; jl++) cst[jl] = 0.f;
    unsigned ph0 = 0, ph1 = 0;

#define ISSUE(c) do {                                                          \
    int _c = (c); unsigned _mb = (_c & 1) ? mbd1 : mbd0;                       \
    unsigned _dst = sA + (unsigned)(_c & 1) * 32768;                           \
    const unsigned char *_sh, *_sl;                                            \
    if (_c < 2) { size_t _o = ((size_t)t * 2 + _c) * 16384;                    \
                  _sh = g_xh + _o; _sl = g_xl + _o; }                          \
    else        { size_t _o = ((size_t)(t - 1) * 8 + (_c - 2)) * 16384;        \
                  _sh = g_hh + _o; _sl = g_hl + _o; }                          \
    expect_tx(_mb, 32768);                                                     \
    bulk_cp(_dst, _sh, 16384, _mb);                                            \
    bulk_cp(_dst + 16384, _sl, 16384, _mb);                                    \
} while (0)

    for (int t = 0; t < TSTEPS; t++) {
        float C0[4] = {0.f, 0.f, 0.f, 0.f};
        float C1[4] = {0.f, 0.f, 0.f, 0.f};
        const int nch = t ? 10 : 2;

        if (tid == 0) { ISSUE(0); ISSUE(1); }
#pragma unroll 1
        for (int ch = 0; ch < nch; ch++) {
            if (ch & 1) { mbar_wait(mbd1, ph1); ph1 ^= 1; }
            else        { mbar_wait(mbd0, ph0); ph0 ^= 1; }
            const unsigned aHi = sA + (unsigned)(ch & 1) * 32768;
            const unsigned chb = (unsigned)ch * 16;
#pragma unroll
            for (int ks = 0; ks < 8; ks++) {
                unsigned Ah[4], Al[4], Bh[4], Bl[4];
                unsigned ku = chb + (unsigned)ks * 2 + kb;
                unsigned offA = (ku ^ (unsigned)r) << 4;
                ldsm4(Ah, rowAhi + offA);
                ldsm4(Al, rowAlo + offA);
                unsigned rowB = aHi + (unsigned)(ks * 16 + krB) * 128 + colB;
                ldsm4t(Bh, rowB);
                ldsm4t(Bl, rowB + 16384);
                mma16816(C0, Ah, Bh[0], Bh[1]);
                mma16816(C0, Ah, Bl[0], Bl[1]);
                mma16816(C0, Al, Bh[0], Bh[1]);
                mma16816(C1, Ah, Bh[2], Bh[3]);
                mma16816(C1, Ah, Bl[2], Bl[3]);
                mma16816(C1, Al, Bh[2], Bh[3]);
            }
            __syncthreads();
            if (tid == 0 && ch + 2 < nch) ISSUE(ch + 2);
        }

        // ---- C exchange (overlay buf0; all chunk reads drained) ----
        {
            const int q = l >> 2, c2 = (l & 3) * 2;
            const int row0 = jt * 16 + q, colb = bt * 16 + c2;
            Dx[row0 * 66 + colb]           = C0[0];
            Dx[row0 * 66 + colb + 1]       = C0[1];
            Dx[(row0 + 8) * 66 + colb]     = C0[2];
            Dx[(row0 + 8) * 66 + colb + 1] = C0[3];
            Dx[row0 * 66 + colb + 8]           = C1[0];
            Dx[row0 * 66 + colb + 9]           = C1[1];
            Dx[(row0 + 8) * 66 + colb + 8]     = C1[2];
            Dx[(row0 + 8) * 66 + colb + 9]     = C1[3];
        }
        __syncthreads();

        if (tid < 64) {
            const int b = tid;
            float z[4][8];
#pragma unroll
            for (int g = 0; g < 4; g++)
#pragma unroll
                for (int jl = 0; jl < 8; jl++)
                    z[g][jl] = Dx[(g * 8 + jl) * 66 + b] + biasSm[g * 8 + jl];
            float hs[8];
#pragma unroll
            for (int jl = 0; jl < 8; jl++) {
                float ff = sigmoid_f(z[0][jl]);
                float ii = sigmoid_f(z[1][jl]);
                float oo = sigmoid_f(z[2][jl]);
                float aa = z[3][jl];
                cst[jl] = ii * tanh_f(aa) + ff * cst[jl];
                hs[jl] = oo * tanh_f(cst[jl]);
            }
            // write h: bf16 hi/lo swizzled act tile + fp32 for out_gemm
            const int hc = j0 >> 7;
            const int klbase = j0 & 127;
            size_t cb = ((size_t)t * 8 + hc) * 16384;
#pragma unroll
            for (int jl = 0; jl < 8; jl++) {
                unsigned short hu, lu;
                split_bf(hs[jl], hu, lu);
                int kl = klbase + jl;
                unsigned us = (unsigned)((b >> 3) ^ jl);
                size_t off = cb + (size_t)kl * 128 + us * 16 + (b & 7) * 2;
                *(unsigned short*)(g_hh + off) = hu;
                *(unsigned short*)(g_hl + off) = lu;
                g_hst[((size_t)t * HDIM + j0 + jl) * BATCH + b] = hs[jl];
            }
            __threadfence();
        }

        __syncthreads();
        if (t < TSTEPS - 1) {
            if (tid == 0) {
                __threadfence();
                int grp = blockIdx.x >> 4;
                unsigned prev = atomicAdd(&g_cnt[grp], 1u);
                if (prev == (unsigned)(t + 1) * 16 - 1) {
                    unsigned pr = atomicAdd(&g_root, 1u);
                    if (pr == (unsigned)(t + 1) * 8 - 1)
                        g_release = (unsigned)(t + 1);
                }
                while (g_release < (unsigned)(t + 1)) { }
                __threadfence();
            }
            __syncthreads();
        }
    }
#undef ISSUE
}

// ===========================================================================
// Kernel 2: out = hs @ fco^T + b (fp32, proven; reads g_hst [t][j][b])
// ===========================================================================
__global__ __launch_bounds__(256) void out_gemm(
    const float* __restrict__ fw, const float* __restrict__ fb,
    float* __restrict__ out)
{
    __shared__ ull As2[16][66];
    __shared__ ull Bs2[16][66];

    const int tid = threadIdx.x;
    const int n0 = blockIdx.x * 64;
    const int m0 = blockIdx.y * 64;
    const int t  = m0 >> 6;
    const int ty = tid >> 4, tx = tid & 15;
    const int kpa = tid >> 4;
    const int b4  = (tid & 15) * 4;

    ull acc[4][4];
#pragma unroll
    for (int i = 0; i < 4; i++)
#pragma unroll
        for (int j = 0; j < 4; j++) acc[i][j] = 0ull;

    for (int k0 = 0; k0 < HDIM; k0 += 32) {
        {
            const float* base = g_hst + ((size_t)t * HDIM + k0 + 2 * kpa) * BATCH + b4;
            float4 ev = *(const float4*)base;
            float4 od = *(const float4*)(base + BATCH);
            As2[kpa][b4 + 0] = pack2(ev.x, od.x);
            As2[kpa][b4 + 1] = pack2(ev.y, od.y);
            As2[kpa][b4 + 2] = pack2(ev.z, od.z);
            As2[kpa][b4 + 3] = pack2(ev.w, od.w);
        }
#pragma unroll
        for (int i = 0; i < 2; i++) {
            int idx = tid + i * 256;
            int rr = idx >> 3, c4 = (idx & 7) * 4;
            int jr = n0 + rr;
            float4 bv = make_float4(0.f, 0.f, 0.f, 0.f);
            if (jr < CDIM)
                bv = *(const float4*)(fw + (size_t)jr * HDIM + k0 + c4);
            Bs2[(c4 >> 1) + 0][rr] = pack2(bv.x, bv.y);
            Bs2[(c4 >> 1) + 1][rr] = pack2(bv.z, bv.w);
        }
        __syncthreads();
#pragma unroll 4
        for (int kk2 = 0; kk2 < 16; kk2++) {
            ulonglong2 rmA = *(const ulonglong2*)&As2[kk2][ty * 4];
            ulonglong2 rmB = *(const ulonglong2*)&As2[kk2][ty * 4 + 2];
            ulonglong2 rnA = *(const ulonglong2*)&Bs2[kk2][tx * 4];
            ulonglong2 rnB = *(const ulonglong2*)&Bs2[kk2][tx * 4 + 2];
            ull rm[4] = { rmA.x, rmA.y, rmB.x, rmB.y };
            ull rn[4] = { rnA.x, rnA.y, rnB.x, rnB.y };
#pragma unroll
            for (int i = 0; i < 4; i++)
#pragma unroll
                for (int j = 0; j < 4; j++)
                    acc[i][j] = fma2(rm[i], rn[j], acc[i][j]);
        }
        __syncthreads();
    }

#pragma unroll
    for (int i = 0; i < 4; i++) {
        int m = m0 + ty * 4 + i;
#pragma unroll
        for (int j = 0; j < 4; j++) {
            int n = n0 + tx * 4 + j;
            if (n < CDIM) {
                float2 v = unpack2(acc[i][j]);
                out[(size_t)m * CDIM + n] = v.x + v.y + fb[n];
            }
        }
    }
}

__global__ void init_k() {
    g_root = 0; g_release = 0;
    for (int i = 0; i < 8; i++) g_cnt[i] = 0;
}

extern "C" void kernel_launch(void* const* d_in, const int* in_sizes, int n_in,
                              void* d_out, int out_size)
{
    const float* x     = (const float*)d_in[0];
    const float* wfx_w = (const float*)d_in[1];
    const float* wfx_b = (const float*)d_in[2];
    const float* wix_w = (const float*)d_in[3];
    const float* wix_b = (const float*)d_in[4];
    const float* wox_w = (const float*)d_in[5];
    const float* wox_b = (const float*)d_in[6];
    const float* wcx_w = (const float*)d_in[7];
    const float* wcx_b = (const float*)d_in[8];
    const float* wfh_w = (const float*)d_in[9];
    const float* wih_w = (const float*)d_in[10];
    const float* woh_w = (const float*)d_in[11];
    const float* wch_w = (const float*)d_in[12];
    const float* fco_w = (const float*)d_in[13];
    const float* fco_b = (const float*)d_in[14];
    float* out = (float*)d_out;

    cudaFuncSetAttribute(lstm_rec, cudaFuncAttributeMaxDynamicSharedMemorySize,
                         SMEM_REC);

    init_k<<<1, 1>>>();
    xsplit<<<TSTEPS, 256>>>(x);
    lstm_rec<<<NCTA, 256, SMEM_REC>>>(
        wfh_w, wih_w, woh_w, wch_w,
        wfx_w, wix_w, wox_w, wcx_w,
        wfx_b, wix_b, wox_b, wcx_b);
    out_gemm<<<dim3((CDIM + 63) / 64, TSTEPS * BATCH / 64), 256>>>(
        fco_w, fco_b, out);
}

// round 12
// speedup vs baseline: 11.1421x; 1.0857x over previous
#include <cuda_runtime.h>
#include <cuda_bf16.h>
#include <math.h>

typedef unsigned long long ull;

#define TSTEPS 512
#define BATCH  64
#define FDIM   256
#define HDIM   1024
#define CDIM   257
#define NCTA   128

// lstm_rec smem layout (bytes)
#define OFF_WHI  0          // W hi: 32 rows x 160 16B-units (80KB), XOR-swizzled
#define OFF_WLO  81920      // W lo (80KB)
#define OFF_A0   163840     // act buf 0: hi 16KB + lo 16KB
#define OFF_A1   196608     // act buf 1
#define OFF_MB   229376     // 2 mbarriers
#define OFF_BIAS 229392     // 32 floats
#define SMEM_REC 229520
#define WPITCH   2560       // W row pitch bytes (1280 k x 2B)

// out_mma smem layout (bytes)
#define OW_HI    0          // FW hi: 32 rows x 128 units (64KB)
#define OW_LO    65536
#define OA0      131072
#define OA1      163840
#define OMB      196608
#define ODX      196640     // 32 x 66 floats
#define SMEM_OUT 205088
#define OW_PITCH 2048
#define TLOOP    8

// ---------------- global scratch ----------------
__device__ __align__(128) unsigned char g_xh[(size_t)TSTEPS * 2 * 16384];
__device__ __align__(128) unsigned char g_xl[(size_t)TSTEPS * 2 * 16384];
__device__ __align__(128) unsigned char g_hh[(size_t)TSTEPS * 8 * 16384];
__device__ __align__(128) unsigned char g_hl[(size_t)TSTEPS * 8 * 16384];
__device__ unsigned g_cnt[8];
__device__ unsigned g_root;
__device__ volatile unsigned g_release;

// ---------------- helpers ----------------
static __device__ __forceinline__ float sigmoid_f(float x) {
    return 1.f / (1.f + __expf(-x));
}
static __device__ __forceinline__ float tanh_f(float x) {
    float e = __expf(2.f * x);
    return 1.f - 2.f / (e + 1.f);
}
static __device__ __forceinline__ unsigned smem_u32(const void* p) {
    return (unsigned)__cvta_generic_to_shared(p);
}
static __device__ __forceinline__ void mbar_init(unsigned a) {
    asm volatile("mbarrier.init.shared.b64 [%0], 1;" :: "r"(a) : "memory");
}
static __device__ __forceinline__ void expect_tx(unsigned mbar, unsigned bytes) {
    asm volatile("mbarrier.arrive.expect_tx.shared.b64 _, [%0], %1;"
                 :: "r"(mbar), "r"(bytes) : "memory");
}
static __device__ __forceinline__ void bulk_cp(unsigned dst, const void* src,
                                               unsigned bytes, unsigned mbar) {
    asm volatile("cp.async.bulk.shared::cluster.global.mbarrier::complete_tx::bytes "
                 "[%0], [%1], %2, [%3];"
                 :: "r"(dst), "l"(src), "r"(bytes), "r"(mbar) : "memory");
}
static __device__ __forceinline__ void mbar_wait(unsigned mbar, unsigned phase) {
    asm volatile(
        "{\n\t.reg .pred P;\n\t"
        "LW_%=:\n\t"
        "mbarrier.try_wait.parity.acquire.cta.shared::cta.b64 P, [%0], %1, 0x989680;\n\t"
        "@P bra LD_%=;\n\t"
        "bra LW_%=;\n\t"
        "LD_%=:\n\t}"
        :: "r"(mbar), "r"(phase) : "memory");
}
static __device__ __forceinline__ void ldsm4(unsigned* r, unsigned addr) {
    asm volatile("ldmatrix.sync.aligned.m8n8.x4.shared.b16 {%0,%1,%2,%3}, [%4];"
                 : "=r"(r[0]), "=r"(r[1]), "=r"(r[2]), "=r"(r[3]) : "r"(addr));
}
static __device__ __forceinline__ void ldsm4t(unsigned* r, unsigned addr) {
    asm volatile("ldmatrix.sync.aligned.m8n8.x4.trans.shared.b16 {%0,%1,%2,%3}, [%4];"
                 : "=r"(r[0]), "=r"(r[1]), "=r"(r[2]), "=r"(r[3]) : "r"(addr));
}
static __device__ __forceinline__ void mma16816(float* c, const unsigned* a,
                                                unsigned b0, unsigned b1) {
    asm volatile(
        "mma.sync.aligned.m16n8k16.row.col.f32.bf16.bf16.f32 "
        "{%0,%1,%2,%3},{%4,%5,%6,%7},{%8,%9},{%0,%1,%2,%3};"
        : "+f"(c[0]), "+f"(c[1]), "+f"(c[2]), "+f"(c[3])
        : "r"(a[0]), "r"(a[1]), "r"(a[2]), "r"(a[3]), "r"(b0), "r"(b1));
}
static __device__ __forceinline__ void split_bf(float v, unsigned short& hi_us,
                                                unsigned short& lo_us) {
    __nv_bfloat16 h = __float2bfloat16(v);
    float hf = __bfloat162float(h);
    __nv_bfloat16 l = __float2bfloat16(v - hf);
    unsigned short hu, lu;
    memcpy(&hu, &h, 2); memcpy(&lu, &l, 2);
    hi_us = hu; lo_us = lu;
}

// ===========================================================================
// Kernel 0: x[t][b][f] fp32 -> swizzled bf16 hi/lo act tiles [t][2ch][128k x 64b]
// ===========================================================================
__global__ __launch_bounds__(256) void xsplit(const float* __restrict__ x)
{
    __shared__ float sx[64][129];
    const int t = blockIdx.x;
    for (int half = 0; half < 2; half++) {
        for (int i = threadIdx.x; i < 64 * 128; i += 256) {
            int b = i >> 7, f = i & 127;
            sx[b][f] = x[((size_t)t * BATCH + b) * FDIM + half * 128 + f];
        }
        __syncthreads();
        if (threadIdx.x < 128) {
            int f = threadIdx.x;
            size_t base = ((size_t)t * 2 + half) * 16384 + (size_t)f * 128;
            for (int b8 = 0; b8 < 8; b8++) {
                unsigned short hu[8], lu[8];
#pragma unroll
                for (int e = 0; e < 8; e++)
                    split_bf(sx[b8 * 8 + e][f], hu[e], lu[e]);
                uint4 hv, lv;
                hv.x = ((unsigned)hu[1] << 16) | hu[0];
                hv.y = ((unsigned)hu[3] << 16) | hu[2];
                hv.z = ((unsigned)hu[5] << 16) | hu[4];
                hv.w = ((unsigned)hu[7] << 16) | hu[6];
                lv.x = ((unsigned)lu[1] << 16) | lu[0];
                lv.y = ((unsigned)lu[3] << 16) | lu[2];
                lv.z = ((unsigned)lu[5] << 16) | lu[4];
                lv.w = ((unsigned)lu[7] << 16) | lu[6];
                unsigned us = (unsigned)(b8 ^ (f & 7));
                *(uint4*)(g_xh + base + us * 16) = hv;
                *(uint4*)(g_xl + base + us * 16) = lv;
            }
        }
        __syncthreads();
    }
}

// ===========================================================================
// Kernel 1: persistent mma.sync (bf16x3) recurrence, split accumulators,
// next-step x copies issued pre-barrier (fly during barrier poll).
// ===========================================================================
__global__ __launch_bounds__(256, 1) void lstm_rec(
    const float* __restrict__ wfh, const float* __restrict__ wih,
    const float* __restrict__ woh, const float* __restrict__ wch,
    const float* __restrict__ wfx, const float* __restrict__ wix,
    const float* __restrict__ wox, const float* __restrict__ wcx,
    const float* __restrict__ bf,  const float* __restrict__ bi,
    const float* __restrict__ bo,  const float* __restrict__ bcv)
{
    extern __shared__ unsigned char sm[];
    const unsigned s0 = smem_u32(sm);
    const unsigned sA = s0 + OFF_A0;
    const unsigned mbd0 = s0 + OFF_MB, mbd1 = s0 + OFF_MB + 8;
    float* biasSm = (float*)(sm + OFF_BIAS);
    float* Dx = (float*)(sm + OFF_A0);           // overlay on act buf 0

    const int tid = threadIdx.x;
    const int j0 = blockIdx.x * 8;
    const float* WH[4] = {wfh, wih, woh, wch};
    const float* WX[4] = {wfx, wix, wox, wcx};
    const float* BS[4] = {bf, bi, bo, bcv};

    if (tid == 0) {
        mbar_init(mbd0); mbar_init(mbd1);
        asm volatile("fence.proxy.async.shared::cta;" ::: "memory");
    }
    if (tid < 32) biasSm[tid] = BS[tid >> 3][j0 + (tid & 7)];

    // ---- weights: 32 rows (g*8+jl) x 1280 k, bf16 hi/lo, unit-swizzled ----
    for (int it = tid; it < 32 * 160; it += 256) {
        int n = it / 160, u = it % 160, k = u * 8;
        int g = n >> 3, jl = n & 7;
        const float* src = (k < 256)
            ? (WX[g] + (size_t)(j0 + jl) * FDIM + k)
            : (WH[g] + (size_t)(j0 + jl) * HDIM + (k - 256));
        float4 v0 = *(const float4*)src;
        float4 v1 = *(const float4*)(src + 4);
        float f[8] = {v0.x, v0.y, v0.z, v0.w, v1.x, v1.y, v1.z, v1.w};
        unsigned short hu[8], lu[8];
#pragma unroll
        for (int e = 0; e < 8; e++) split_bf(f[e], hu[e], lu[e]);
        uint4 hv, lv;
        hv.x = ((unsigned)hu[1] << 16) | hu[0]; hv.y = ((unsigned)hu[3] << 16) | hu[2];
        hv.z = ((unsigned)hu[5] << 16) | hu[4]; hv.w = ((unsigned)hu[7] << 16) | hu[6];
        lv.x = ((unsigned)lu[1] << 16) | lu[0]; lv.y = ((unsigned)lu[3] << 16) | lu[2];
        lv.z = ((unsigned)lu[5] << 16) | lu[4]; lv.w = ((unsigned)lu[7] << 16) | lu[6];
        unsigned off = (unsigned)n * WPITCH + (unsigned)(u ^ (n & 7)) * 16;
        *(uint4*)(sm + OFF_WHI + off) = hv;
        *(uint4*)(sm + OFF_WLO + off) = lv;
    }
    __syncthreads();

    // ---- per-lane fragment addressing constants ----
    const int l = tid & 31, wid = tid >> 5;
    const int jt = wid >> 2, bt = wid & 3;
    const int mi = l >> 3, r = l & 7;
    const int jloc = jt * 16 + (mi & 1) * 8 + r;
    const unsigned rowAhi = s0 + OFF_WHI + (unsigned)jloc * WPITCH;
    const unsigned rowAlo = s0 + OFF_WLO + (unsigned)jloc * WPITCH;
    const unsigned kb = (unsigned)(mi >> 1);
    const unsigned colB = ((unsigned)((bt * 2 + (mi >> 1)) ^ r)) << 4;
    const int krB = (mi & 1) * 8 + r;

    float cst[8];
#pragma unroll
    for (int jl = 0; jl < 8; jl++) cst[jl] = 0.f;
    unsigned ph0 = 0, ph1 = 0;

    // c = chunk position within step st: 0,1 = x(st); 2..9 = h chunk c-2 of st-1
#define ISSUE_C(st, c) do {                                                    \
    int _c = (c); unsigned _mb = (_c & 1) ? mbd1 : mbd0;                       \
    unsigned _dst = sA + (unsigned)(_c & 1) * 32768;                           \
    const unsigned char *_sh, *_sl;                                            \
    if (_c < 2) { size_t _o = ((size_t)(st) * 2 + _c) * 16384;                 \
                  _sh = g_xh + _o; _sl = g_xl + _o; }                          \
    else        { size_t _o = ((size_t)((st) - 1) * 8 + (_c - 2)) * 16384;     \
                  _sh = g_hh + _o; _sl = g_hl + _o; }                          \
    expect_tx(_mb, 32768);                                                     \
    bulk_cp(_dst, _sh, 16384, _mb);                                            \
    bulk_cp(_dst + 16384, _sl, 16384, _mb);                                    \
} while (0)

    for (int t = 0; t < TSTEPS; t++) {
        float C0h[4] = {0.f, 0.f, 0.f, 0.f};
        float C0l[4] = {0.f, 0.f, 0.f, 0.f};
        float C1h[4] = {0.f, 0.f, 0.f, 0.f};
        float C1l[4] = {0.f, 0.f, 0.f, 0.f};
        const int nch = t ? 10 : 2;

        if (t == 0 && tid == 0) { ISSUE_C(0, 0); ISSUE_C(0, 1); }
#pragma unroll 1
        for (int ch = 0; ch < nch; ch++) {
            if (ch & 1) { mbar_wait(mbd1, ph1); ph1 ^= 1; }
            else        { mbar_wait(mbd0, ph0); ph0 ^= 1; }
            const unsigned aHi = sA + (unsigned)(ch & 1) * 32768;
            const unsigned chb = (unsigned)ch * 16;
#pragma unroll
            for (int ks = 0; ks < 8; ks++) {
                unsigned Ah[4], Al[4], Bh[4], Bl[4];
                unsigned ku = chb + (unsigned)ks * 2 + kb;
                unsigned offA = (ku ^ (unsigned)r) << 4;
                ldsm4(Ah, rowAhi + offA);
                ldsm4(Al, rowAlo + offA);
                unsigned rowB = aHi + (unsigned)(ks * 16 + krB) * 128 + colB;
                ldsm4t(Bh, rowB);
                ldsm4t(Bl, rowB + 16384);
                mma16816(C0h, Ah, Bh[0], Bh[1]);
                mma16816(C1h, Ah, Bh[2], Bh[3]);
                mma16816(C0l, Ah, Bl[0], Bl[1]);
                mma16816(C1l, Ah, Bl[2], Bl[3]);
                mma16816(C0l, Al, Bh[0], Bh[1]);
                mma16816(C1l, Al, Bh[2], Bh[3]);
            }
            __syncthreads();
            if (tid == 0 && ch + 2 < nch) ISSUE_C(t, ch + 2);
        }

        // ---- C exchange (overlay buf0; all chunk reads drained) ----
        {
            const int q = l >> 2, c2 = (l & 3) * 2;
            const int row0 = jt * 16 + q, colb = bt * 16 + c2;
            Dx[row0 * 66 + colb]           = C0h[0] + C0l[0];
            Dx[row0 * 66 + colb + 1]       = C0h[1] + C0l[1];
            Dx[(row0 + 8) * 66 + colb]     = C0h[2] + C0l[2];
            Dx[(row0 + 8) * 66 + colb + 1] = C0h[3] + C0l[3];
            Dx[row0 * 66 + colb + 8]           = C1h[0] + C1l[0];
            Dx[row0 * 66 + colb + 9]           = C1h[1] + C1l[1];
            Dx[(row0 + 8) * 66 + colb + 8]     = C1h[2] + C1l[2];
            Dx[(row0 + 8) * 66 + colb + 9]     = C1h[3] + C1l[3];
        }
        __syncthreads();

        if (tid < 64) {
            const int b = tid;
            float z[4][8];
#pragma unroll
            for (int g = 0; g < 4; g++)
#pragma unroll
                for (int jl = 0; jl < 8; jl++)
                    z[g][jl] = Dx[(g * 8 + jl) * 66 + b] + biasSm[g * 8 + jl];
            float hs[8];
#pragma unroll
            for (int jl = 0; jl < 8; jl++) {
                float ff = sigmoid_f(z[0][jl]);
                float ii = sigmoid_f(z[1][jl]);
                float oo = sigmoid_f(z[2][jl]);
                float aa = z[3][jl];
                cst[jl] = ii * tanh_f(aa) + ff * cst[jl];
                hs[jl] = oo * tanh_f(cst[jl]);
            }
            // write h as bf16 hi/lo swizzled act tile (next step's B operand)
            const int hc = j0 >> 7;
            const int klbase = j0 & 127;
            size_t cb = ((size_t)t * 8 + hc) * 16384;
#pragma unroll
            for (int jl = 0; jl < 8; jl++) {
                unsigned short hu, lu;
                split_bf(hs[jl], hu, lu);
                int kl = klbase + jl;
                unsigned us = (unsigned)((b >> 3) ^ jl);
                size_t off = cb + (size_t)kl * 128 + us * 16 + (b & 7) * 2;
                *(unsigned short*)(g_hh + off) = hu;
                *(unsigned short*)(g_hl + off) = lu;
            }
            __threadfence();
        }

        __syncthreads();   // Dx reads done; pending STS drained (BAR drains STS)
        if (t < TSTEPS - 1) {
            if (tid == 0) {
                // issue next step's x chunks NOW — they fly during barrier poll
                ISSUE_C(t + 1, 0); ISSUE_C(t + 1, 1);
                __threadfence();
                int grp = blockIdx.x >> 4;
                unsigned prev = atomicAdd(&g_cnt[grp], 1u);
                if (prev == (unsigned)(t + 1) * 16 - 1) {
                    unsigned pr = atomicAdd(&g_root, 1u);
                    if (pr == (unsigned)(t + 1) * 8 - 1)
                        g_release = (unsigned)(t + 1);
                }
                while (g_release < (unsigned)(t + 1)) { }
                __threadfence();
            }
            __syncthreads();
        }
    }
#undef ISSUE_C
}

// ===========================================================================
// Kernel 2: out = hs @ fco^T + b on tensor cores (bf16x3).
// CTA = (ntile, tgroup): D[32n x 64b] = FW[32x1024] * H[1024x64] per t,
// TLOOP=8 timesteps per CTA. B operand = g_hh/g_hl tiles (same as rec).
// ===========================================================================
__global__ __launch_bounds__(256, 1) void out_mma(
    const float* __restrict__ fw, const float* __restrict__ fb,
    float* __restrict__ out)
{
    extern __shared__ unsigned char sm[];
    const unsigned s0 = smem_u32(sm);
    const unsigned sA = s0 + OA0;
    const unsigned mb0 = s0 + OMB, mb1 = s0 + OMB + 8;
    float* Dx = (float*)(sm + ODX);

    const int tid = threadIdx.x;
    const int n0 = blockIdx.x * 32;
    const int t0 = blockIdx.y * TLOOP;

    if (tid == 0) {
        mbar_init(mb0); mbar_init(mb1);
        asm volatile("fence.proxy.async.shared::cta;" ::: "memory");
        // start copies for first t while weights load
        size_t o0 = ((size_t)t0 * 8 + 0) * 16384;
        size_t o1 = ((size_t)t0 * 8 + 1) * 16384;
        expect_tx(mb0, 32768);
        bulk_cp(sA,         g_hh + o0, 16384, mb0);
        bulk_cp(sA + 16384, g_hl + o0, 16384, mb0);
        expect_tx(mb1, 32768);
        bulk_cp(sA + 32768, g_hh + o1, 16384, mb1);
        bulk_cp(sA + 49152, g_hl + o1, 16384, mb1);
    }

    // FW rows n0..n0+31 -> bf16 hi/lo swizzled (zeros beyond CDIM)
    for (int it = tid; it < 32 * 128; it += 256) {
        int n = it >> 7, u = it & 127, k = u * 8;
        int row = n0 + n;
        float f[8] = {0.f, 0.f, 0.f, 0.f, 0.f, 0.f, 0.f, 0.f};
        if (row < CDIM) {
            const float* src = fw + (size_t)row * HDIM + k;
            float4 v0 = *(const float4*)src;
            float4 v1 = *(const float4*)(src + 4);
            f[0] = v0.x; f[1] = v0.y; f[2] = v0.z; f[3] = v0.w;
            f[4] = v1.x; f[5] = v1.y; f[6] = v1.z; f[7] = v1.w;
        }
        unsigned short hu[8], lu[8];
#pragma unroll
        for (int e = 0; e < 8; e++) split_bf(f[e], hu[e], lu[e]);
        uint4 hv, lv;
        hv.x = ((unsigned)hu[1] << 16) | hu[0]; hv.y = ((unsigned)hu[3] << 16) | hu[2];
        hv.z = ((unsigned)hu[5] << 16) | hu[4]; hv.w = ((unsigned)hu[7] << 16) | hu[6];
        lv.x = ((unsigned)lu[1] << 16) | lu[0]; lv.y = ((unsigned)lu[3] << 16) | lu[2];
        lv.z = ((unsigned)lu[5] << 16) | lu[4]; lv.w = ((unsigned)lu[7] << 16) | lu[6];
        unsigned off = (unsigned)n * OW_PITCH + (unsigned)(u ^ (n & 7)) * 16;
        *(uint4*)(sm + OW_HI + off) = hv;
        *(uint4*)(sm + OW_LO + off) = lv;
    }
    __syncthreads();

    const int l = tid & 31, wid = tid >> 5;
    const int jt = wid >> 2, bt = wid & 3;
    const int mi = l >> 3, r = l & 7;
    const int nloc = jt * 16 + (mi & 1) * 8 + r;
    const unsigned rowAhi = s0 + OW_HI + (unsigned)nloc * OW_PITCH;
    const unsigned rowAlo = s0 + OW_LO + (unsigned)nloc * OW_PITCH;
    const unsigned kb = (unsigned)(mi >> 1);
    const unsigned colB = ((unsigned)((bt * 2 + (mi >> 1)) ^ r)) << 4;
    const int krB = (mi & 1) * 8 + r;

    unsigned ph0 = 0, ph1 = 0;

#define OISSUE(tt_, c_) do {                                                   \
    int _c = (c_); unsigned _mb = (_c & 1) ? mb1 : mb0;                        \
    unsigned _dst = sA + (unsigned)(_c & 1) * 32768;                           \
    size_t _o = ((size_t)(tt_) * 8 + _c) * 16384;                              \
    expect_tx(_mb, 32768);                                                     \
    bulk_cp(_dst, g_hh + _o, 16384, _mb);                                      \
    bulk_cp(_dst + 16384, g_hl + _o, 16384, _mb);                              \
} while (0)

    for (int tt = 0; tt < TLOOP; tt++) {
        const int t = t0 + tt;
        float C0h[4] = {0.f, 0.f, 0.f, 0.f};
        float C0l[4] = {0.f, 0.f, 0.f, 0.f};
        float C1h[4] = {0.f, 0.f, 0.f, 0.f};
        float C1l[4] = {0.f, 0.f, 0.f, 0.f};
#pragma unroll 1
        for (int ch = 0; ch < 8; ch++) {
            if (ch & 1) { mbar_wait(mb1, ph1); ph1 ^= 1; }
            else        { mbar_wait(mb0, ph0); ph0 ^= 1; }
            const unsigned aHi = sA + (unsigned)(ch & 1) * 32768;
            const unsigned chb = (unsigned)ch * 16;
#pragma unroll
            for (int ks = 0; ks < 8; ks++) {
                unsigned Ah[4], Al[4], Bh[4], Bl[4];
                unsigned ku = chb + (unsigned)ks * 2 + kb;
                unsigned offA = (ku ^ (unsigned)r) << 4;
                ldsm4(Ah, rowAhi + offA);
                ldsm4(Al, rowAlo + offA);
                unsigned rowB = aHi + (unsigned)(ks * 16 + krB) * 128 + colB;
                ldsm4t(Bh, rowB);
                ldsm4t(Bl, rowB + 16384);
                mma16816(C0h, Ah, Bh[0], Bh[1]);
                mma16816(C1h, Ah, Bh[2], Bh[3]);
                mma16816(C0l, Ah, Bl[0], Bl[1]);
                mma16816(C1l, Ah, Bl[2], Bl[3]);
                mma16816(C0l, Al, Bh[0], Bh[1]);
                mma16816(C1l, Al, Bh[2], Bh[3]);
            }
            __syncthreads();
            if (tid == 0) {
                int nxt = ch + 2;
                if (nxt < 8) OISSUE(t, nxt);
                else if (tt + 1 < TLOOP) OISSUE(t + 1, nxt - 8);
            }
        }
        // exchange
        {
            const int q = l >> 2, c2 = (l & 3) * 2;
            const int row0 = jt * 16 + q, colb = bt * 16 + c2;
            Dx[row0 * 66 + colb]           = C0h[0] + C0l[0];
            Dx[row0 * 66 + colb + 1]       = C0h[1] + C0l[1];
            Dx[(row0 + 8) * 66 + colb]     = C0h[2] + C0l[2];
            Dx[(row0 + 8) * 66 + colb + 1] = C0h[3] + C0l[3];
            Dx[row0 * 66 + colb + 8]           = C1h[0] + C1l[0];
            Dx[row0 * 66 + colb + 9]           = C1h[1] + C1l[1];
            Dx[(row0 + 8) * 66 + colb + 8]     = C1h[2] + C1l[2];
            Dx[(row0 + 8) * 66 + colb + 9]     = C1h[3] + C1l[3];
        }
        __syncthreads();
        // store: thread (b = tid&63, nq = tid>>6) writes 8 n values
        {
            const int b = tid & 63, nq = tid >> 6;
#pragma unroll
            for (int e = 0; e < 8; e++) {
                int nl = nq * 8 + e, n = n0 + nl;
                if (n < CDIM)
                    out[((size_t)t * BATCH + b) * CDIM + n] =
                        Dx[nl * 66 + b] + fb[n];
            }
        }
    }
#undef OISSUE
}

__global__ void init_k() {
    g_root = 0; g_release = 0;
    for (int i = 0; i < 8; i++) g_cnt[i] = 0;
}

extern "C" void kernel_launch(void* const* d_in, const int* in_sizes, int n_in,
                              void* d_out, int out_size)
{
    const float* x     = (const float*)d_in[0];
    const float* wfx_w = (const float*)d_in[1];
    const float* wfx_b = (const float*)d_in[2];
    const float* wix_w = (const float*)d_in[3];
    const float* wix_b = (const float*)d_in[4];
    const float* wox_w = (const float*)d_in[5];
    const float* wox_b = (const float*)d_in[6];
    const float* wcx_w = (const float*)d_in[7];
    const float* wcx_b = (const float*)d_in[8];
    const float* wfh_w = (const float*)d_in[9];
    const float* wih_w = (const float*)d_in[10];
    const float* woh_w = (const float*)d_in[11];
    const float* wch_w = (const float*)d_in[12];
    const float* fco_w = (const float*)d_in[13];
    const float* fco_b = (const float*)d_in[14];
    float* out = (float*)d_out;

    cudaFuncSetAttribute(lstm_rec, cudaFuncAttributeMaxDynamicSharedMemorySize,
                         SMEM_REC);
    cudaFuncSetAttribute(out_mma, cudaFuncAttributeMaxDynamicSharedMemorySize,
                         SMEM_OUT);

    init_k<<<1, 1>>>();
    xsplit<<<TSTEPS, 256>>>(x);
    lstm_rec<<<NCTA, 256, SMEM_REC>>>(
        wfh_w, wih_w, woh_w, wch_w,
        wfx_w, wix_w, wox_w, wcx_w,
        wfx_b, wix_b, wox_b, wcx_b);
    out_mma<<<dim3(9, TSTEPS / TLOOP), 256, SMEM_OUT>>>(fco_w, fco_b, out);
}